// round 3
// baseline (speedup 1.0000x reference)
#include <cuda_runtime.h>
#include <math.h>

// Problem constants
#define Bsz   2
#define Sseq  1024
#define Dm    1024
#define Hh    16
#define HDd   64
#define WIN   256
#define FFN_D 4096
#define NTOK  (Bsz * Sseq)   // 2048

// ---------------- scratch (no allocation allowed -> __device__ globals) ----------
__device__ float g_h   [NTOK * Dm];
__device__ float g_q   [NTOK * Dm];
__device__ float g_k   [NTOK * Dm];
__device__ float g_v   [NTOK * Dm];
__device__ float g_ctx [NTOK * Dm];
__device__ float g_x1  [NTOK * Dm];
__device__ float g_h2  [NTOK * Dm];
__device__ float g_gate[NTOK * FFN_D];
__device__ float g_up  [NTOK * FFN_D];
__device__ float g_act [NTOK * FFN_D];

// ---------------- RMSNorm: one block per token row ------------------------------
__global__ __launch_bounds__(256) void rmsnorm_kernel(
    const float* __restrict__ x, const float* __restrict__ w, float* __restrict__ o)
{
    int row = blockIdx.x;
    const float* xr = x + (size_t)row * Dm;
    float vals[4];
    float s = 0.f;
    int j = 0;
    for (int i = threadIdx.x; i < Dm; i += 256, j++) {
        float vv = xr[i];
        vals[j] = vv;
        s += vv * vv;
    }
    #pragma unroll
    for (int off = 16; off > 0; off >>= 1)
        s += __shfl_xor_sync(0xffffffffu, s, off);
    __shared__ float red[8];
    if ((threadIdx.x & 31) == 0) red[threadIdx.x >> 5] = s;
    __syncthreads();
    float tot = 0.f;
    #pragma unroll
    for (int i = 0; i < 8; i++) tot += red[i];
    float sc = rsqrtf(tot * (1.0f / Dm) + 1e-6f);
    float* orow = o + (size_t)row * Dm;
    j = 0;
    for (int i = threadIdx.x; i < Dm; i += 256, j++)
        orow[i] = vals[j] * sc * w[i];
}

// ---------------- Generic NT GEMM: C[M,N] = A[M,K] * B[N,K]^T (+bias)(+res) -----
#define GBM 128
#define GBN 128
#define GBK 16

__global__ __launch_bounds__(256) void gemm_nt_kernel(
    const float* __restrict__ A, const float* __restrict__ B,
    const float* __restrict__ bias, const float* __restrict__ res,
    float* __restrict__ C, int M, int N, int K)
{
    __shared__ float As[GBK][GBM + 4];
    __shared__ float Bs[GBK][GBN + 4];
    int tid = threadIdx.x;
    int bm = blockIdx.y * GBM;
    int bn = blockIdx.x * GBN;
    int tx = tid & 15, ty = tid >> 4;

    float acc[8][8];
    #pragma unroll
    for (int i = 0; i < 8; i++)
        #pragma unroll
        for (int jj = 0; jj < 8; jj++) acc[i][jj] = 0.f;

    const float* Ab = A + (size_t)bm * K;
    const float* Bb = B + (size_t)bn * K;

    for (int k0 = 0; k0 < K; k0 += GBK) {
        #pragma unroll
        for (int i = 0; i < 2; i++) {
            int idx = tid + i * 256;
            int r  = idx >> 2;
            int c4 = (idx & 3) << 2;
            float4 a = *(const float4*)(Ab + (size_t)r * K + k0 + c4);
            As[c4 + 0][r] = a.x; As[c4 + 1][r] = a.y;
            As[c4 + 2][r] = a.z; As[c4 + 3][r] = a.w;
            float4 b = *(const float4*)(Bb + (size_t)r * K + k0 + c4);
            Bs[c4 + 0][r] = b.x; Bs[c4 + 1][r] = b.y;
            Bs[c4 + 2][r] = b.z; Bs[c4 + 3][r] = b.w;
        }
        __syncthreads();
        #pragma unroll
        for (int k = 0; k < GBK; k++) {
            float a[8], b[8];
            *(float4*)(a)     = *(const float4*)&As[k][ty * 8];
            *(float4*)(a + 4) = *(const float4*)&As[k][ty * 8 + 4];
            *(float4*)(b)     = *(const float4*)&Bs[k][tx * 8];
            *(float4*)(b + 4) = *(const float4*)&Bs[k][tx * 8 + 4];
            #pragma unroll
            for (int i = 0; i < 8; i++)
                #pragma unroll
                for (int jj = 0; jj < 8; jj++)
                    acc[i][jj] += a[i] * b[jj];
        }
        __syncthreads();
    }

    #pragma unroll
    for (int i = 0; i < 8; i++) {
        int row = bm + ty * 8 + i;
        float* Cr = C + (size_t)row * N;
        const float* Rr = res ? (res + (size_t)row * N) : nullptr;
        #pragma unroll
        for (int jj = 0; jj < 8; jj++) {
            int col = bn + tx * 8 + jj;
            float vv = acc[i][jj];
            if (bias) vv += bias[col];
            if (Rr)   vv += Rr[col];
            Cr[col] = vv;
        }
    }
}

// ---------------- RoPE (in-place on q and k, [NTOK, D] layout) -------------------
__global__ __launch_bounds__(256) void rope_kernel(float* __restrict__ q, float* __restrict__ k)
{
    int gid = blockIdx.x * 256 + threadIdx.x;   // NTOK * 512 total
    int r   = gid >> 9;                         // token row
    int rem = gid & 511;
    int h   = rem >> 5;
    int d   = rem & 31;
    int s   = r & (Sseq - 1);
    // inv_freq = 10000^(-d/32)
    float inv = expf(-(float)d * (9.210340371976184f / 32.0f));
    float ang = (float)s * inv;
    float sn, cs;
    sincosf(ang, &sn, &cs);
    size_t base = (size_t)r * Dm + h * HDd + d;
    float q1 = q[base], q2 = q[base + 32];
    q[base]      = q1 * cs - q2 * sn;
    q[base + 32] = q2 * cs + q1 * sn;
    float k1 = k[base], k2 = k[base + 32];
    k[base]      = k1 * cs - k2 * sn;
    k[base + 32] = k2 * cs + k1 * sn;
}

// ---------------- Sliding-window attention ---------------------------------------
// Block = (b, h, 64-query tile). Key span = [q0-255, q0+63] -> 320 slots.
// Dense attn probs written to global (rest is pre-zeroed by memset).
#define QT      64
#define KSPAN   320
#define PSTRIDE 321
#define TSTRIDE 68

__global__ __launch_bounds__(256) void attn_kernel(
    const float* __restrict__ q, const float* __restrict__ k, const float* __restrict__ v,
    float* __restrict__ attn, float* __restrict__ ctx)
{
    extern __shared__ float sm[];
    float* Ps = sm;                              // [64][321] scores -> probs
    float* Qs = sm + QT * PSTRIDE;               // [64 d][68]  (transposed: Qs[d][qi])
    float* Cs = Qs + HDd * TSTRIDE;              // chunk buffer [64][68]

    int blk = blockIdx.x;
    int qt = blk & 15;
    int h  = (blk >> 4) & 15;
    int b  = blk >> 8;
    int q0 = qt * QT;
    int kb = q0 - (WIN - 1);                     // may be negative
    int tid = threadIdx.x;
    int tx = tid & 15, ty = tid >> 4;
    const float scale = 0.125f;                  // 1/sqrt(64)

    // load Q tile transposed: Qs[d][qi]
    for (int idx = tid; idx < QT * HDd; idx += 256) {
        int qi = idx >> 6, d = idx & 63;
        Qs[d * TSTRIDE + qi] = q[(size_t)(b * Sseq + q0 + qi) * Dm + h * HDd + d];
    }

    // ---- phase 1: raw scores over 5 key chunks of 64 ----
    for (int c = 0; c < 5; c++) {
        // load K chunk transposed: Cs[d][jj] (zero-fill out of range)
        for (int idx = tid; idx < 64 * HDd; idx += 256) {
            int jj = idx >> 6, d = idx & 63;
            int jg = kb + c * 64 + jj;
            float kv = (jg >= 0 && jg < Sseq)
                       ? k[(size_t)(b * Sseq + jg) * Dm + h * HDd + d] : 0.f;
            Cs[d * TSTRIDE + jj] = kv;
        }
        __syncthreads();
        float acc[4][4] = {{0.f}};
        #pragma unroll 4
        for (int d = 0; d < HDd; d++) {
            float a4[4], b4[4];
            *(float4*)a4 = *(const float4*)&Qs[d * TSTRIDE + ty * 4];
            *(float4*)b4 = *(const float4*)&Cs[d * TSTRIDE + tx * 4];
            #pragma unroll
            for (int i = 0; i < 4; i++)
                #pragma unroll
                for (int jj = 0; jj < 4; jj++)
                    acc[i][jj] += a4[i] * b4[jj];
        }
        #pragma unroll
        for (int i = 0; i < 4; i++)
            #pragma unroll
            for (int jj = 0; jj < 4; jj++)
                Ps[(ty * 4 + i) * PSTRIDE + c * 64 + tx * 4 + jj] = acc[i][jj] * scale;
        __syncthreads();
    }

    // ---- phase 2: softmax per query row (warp per row) + dense write ----
    int warp = tid >> 5, lane = tid & 31;
    for (int qi = warp; qi < QT; qi += 8) {
        int i = q0 + qi;
        int colLo = qi;
        if (-kb > colLo) colLo = -kb;            // enforce j >= 0
        int colHi = qi + (WIN - 1);
        float* prow = Ps + qi * PSTRIDE;
        float m = -1e30f;
        for (int c = lane; c < KSPAN; c += 32)
            if (c >= colLo && c <= colHi) m = fmaxf(m, prow[c]);
        #pragma unroll
        for (int off = 16; off > 0; off >>= 1)
            m = fmaxf(m, __shfl_xor_sync(0xffffffffu, m, off));
        float ssum = 0.f;
        for (int c = lane; c < KSPAN; c += 32) {
            float p = 0.f;
            if (c >= colLo && c <= colHi) p = __expf(prow[c] - m);
            prow[c] = p;
            ssum += p;
        }
        #pragma unroll
        for (int off = 16; off > 0; off >>= 1)
            ssum += __shfl_xor_sync(0xffffffffu, ssum, off);
        float inv = 1.f / ssum;
        float* arow = attn + ((size_t)((b * Hh + h) * Sseq + i)) * Sseq;
        for (int c = lane; c < KSPAN; c += 32) {
            float p = prow[c] * inv;
            prow[c] = p;
            if (c >= colLo && c <= colHi) arow[kb + c] = p;
        }
    }
    __syncthreads();

    // ---- phase 3: ctx = P @ V over 5 value chunks ----
    float acc[4][4] = {{0.f}};
    for (int c = 0; c < 5; c++) {
        // load V chunk natural layout: Cs[jj][d]
        for (int idx = tid; idx < 64 * HDd; idx += 256) {
            int jj = idx >> 6, d = idx & 63;
            int jg = kb + c * 64 + jj;
            float vv = (jg >= 0 && jg < Sseq)
                       ? v[(size_t)(b * Sseq + jg) * Dm + h * HDd + d] : 0.f;
            Cs[jj * TSTRIDE + d] = vv;
        }
        __syncthreads();
        #pragma unroll 4
        for (int kk = 0; kk < 64; kk++) {
            float4 vv = *(const float4*)&Cs[kk * TSTRIDE + tx * 4];
            #pragma unroll
            for (int i = 0; i < 4; i++) {
                float p = Ps[(ty * 4 + i) * PSTRIDE + c * 64 + kk];
                acc[i][0] += p * vv.x;
                acc[i][1] += p * vv.y;
                acc[i][2] += p * vv.z;
                acc[i][3] += p * vv.w;
            }
        }
        __syncthreads();
    }
    #pragma unroll
    for (int i = 0; i < 4; i++) {
        int row = b * Sseq + q0 + ty * 4 + i;
        float4 o;
        o.x = acc[i][0]; o.y = acc[i][1]; o.z = acc[i][2]; o.w = acc[i][3];
        *(float4*)&ctx[(size_t)row * Dm + h * HDd + tx * 4] = o;
    }
}

// ---------------- SiLU(gate) * up ------------------------------------------------
__global__ __launch_bounds__(256) void silu_mul_kernel(
    const float* __restrict__ g, const float* __restrict__ u, float* __restrict__ o, int n)
{
    int i = blockIdx.x * 256 + threadIdx.x;
    if (i < n) {
        float a = g[i];
        o[i] = a / (1.f + expf(-a)) * u[i];
    }
}

// ---------------- launch ---------------------------------------------------------
extern "C" void kernel_launch(void* const* d_in, const int* in_sizes, int n_in,
                              void* d_out, int out_size)
{
    const float* x   = (const float*)d_in[0];
    const float* wq  = (const float*)d_in[1];
    const float* bq  = (const float*)d_in[2];
    const float* wk  = (const float*)d_in[3];
    const float* bk  = (const float*)d_in[4];
    const float* wv  = (const float*)d_in[5];
    const float* bv  = (const float*)d_in[6];
    const float* wo  = (const float*)d_in[7];
    const float* bo  = (const float*)d_in[8];
    const float* anw = (const float*)d_in[9];
    const float* fnw = (const float*)d_in[10];
    const float* gw  = (const float*)d_in[11];
    const float* uw  = (const float*)d_in[12];
    const float* dw  = (const float*)d_in[13];

    float* out_x    = (float*)d_out;
    float* out_attn = out_x + (size_t)NTOK * Dm;

    float *h, *qp, *kp, *vp, *ctx, *x1, *h2, *gt, *up, *act;
    cudaGetSymbolAddress((void**)&h,   g_h);
    cudaGetSymbolAddress((void**)&qp,  g_q);
    cudaGetSymbolAddress((void**)&kp,  g_k);
    cudaGetSymbolAddress((void**)&vp,  g_v);
    cudaGetSymbolAddress((void**)&ctx, g_ctx);
    cudaGetSymbolAddress((void**)&x1,  g_x1);
    cudaGetSymbolAddress((void**)&h2,  g_h2);
    cudaGetSymbolAddress((void**)&gt,  g_gate);
    cudaGetSymbolAddress((void**)&up,  g_up);
    cudaGetSymbolAddress((void**)&act, g_act);

    // attn-norm
    rmsnorm_kernel<<<NTOK, 256>>>(x, anw, h);

    // QKV projections
    dim3 g1(Dm / GBN, NTOK / GBM);      // (8, 16)
    gemm_nt_kernel<<<g1, 256>>>(h, wq, bq, nullptr, qp, NTOK, Dm, Dm);
    gemm_nt_kernel<<<g1, 256>>>(h, wk, bk, nullptr, kp, NTOK, Dm, Dm);
    gemm_nt_kernel<<<g1, 256>>>(h, wv, bv, nullptr, vp, NTOK, Dm, Dm);

    // RoPE on q and k
    rope_kernel<<<(NTOK * 512) / 256, 256>>>(qp, kp);

    // zero dense attn output, then windowed attention
    cudaMemsetAsync(out_attn, 0, (size_t)Bsz * Hh * Sseq * Sseq * sizeof(float), 0);
    int smemBytes = (QT * PSTRIDE + 2 * 64 * TSTRIDE) * (int)sizeof(float);
    cudaFuncSetAttribute(attn_kernel, cudaFuncAttributeMaxDynamicSharedMemorySize, smemBytes);
    attn_kernel<<<Bsz * Hh * (Sseq / QT), 256, smemBytes>>>(qp, kp, vp, out_attn, ctx);

    // output projection + residual
    gemm_nt_kernel<<<g1, 256>>>(ctx, wo, bo, x, x1, NTOK, Dm, Dm);

    // ffn-norm
    rmsnorm_kernel<<<NTOK, 256>>>(x1, fnw, h2);

    // FFN
    dim3 g2(FFN_D / GBN, NTOK / GBM);   // (32, 16)
    gemm_nt_kernel<<<g2, 256>>>(h2, gw, nullptr, nullptr, gt, NTOK, FFN_D, Dm);
    gemm_nt_kernel<<<g2, 256>>>(h2, uw, nullptr, nullptr, up, NTOK, FFN_D, Dm);
    silu_mul_kernel<<<(NTOK * FFN_D) / 256, 256>>>(gt, up, act, NTOK * FFN_D);
    gemm_nt_kernel<<<g1, 256>>>(act, dw, nullptr, x1, out_x, NTOK, Dm, FFN_D);
}

// round 5
// speedup vs baseline: 1.7708x; 1.7708x over previous
#include <cuda_runtime.h>
#include <math.h>
#include <stdint.h>

// Problem constants
#define Bsz   2
#define Sseq  1024
#define Dm    1024
#define Hh    16
#define HDd   64
#define WIN   256
#define FFN_D 4096
#define NTOK  (Bsz * Sseq)   // 2048

// ---------------- scratch (no allocation allowed -> __device__ globals) ----------
__device__ float g_h   [NTOK * Dm];
__device__ float g_q   [NTOK * Dm];
__device__ float g_k   [NTOK * Dm];
__device__ float g_v   [NTOK * Dm];
__device__ float g_ctx [NTOK * Dm];
__device__ float g_x1  [NTOK * Dm];
__device__ float g_h2  [NTOK * Dm];
__device__ float g_gate[NTOK * FFN_D];
__device__ float g_up  [NTOK * FFN_D];
__device__ float g_act [NTOK * FFN_D];

// ---------------- RMSNorm: one block per token row ------------------------------
__global__ __launch_bounds__(256) void rmsnorm_kernel(
    const float* __restrict__ x, const float* __restrict__ w, float* __restrict__ o)
{
    int row = blockIdx.x;
    const float* xr = x + (size_t)row * Dm;
    float vals[4];
    float s = 0.f;
    int j = 0;
    for (int i = threadIdx.x; i < Dm; i += 256, j++) {
        float vv = xr[i];
        vals[j] = vv;
        s += vv * vv;
    }
    #pragma unroll
    for (int off = 16; off > 0; off >>= 1)
        s += __shfl_xor_sync(0xffffffffu, s, off);
    __shared__ float red[8];
    if ((threadIdx.x & 31) == 0) red[threadIdx.x >> 5] = s;
    __syncthreads();
    float tot = 0.f;
    #pragma unroll
    for (int i = 0; i < 8; i++) tot += red[i];
    float sc = rsqrtf(tot * (1.0f / Dm) + 1e-6f);
    float* orow = o + (size_t)row * Dm;
    j = 0;
    for (int i = threadIdx.x; i < Dm; i += 256, j++)
        orow[i] = vals[j] * sc * w[i];
}

// ---------------- tf32 tensor-core NT GEMM ---------------------------------------
// C[M,N] = A[M,K] * B[N,K]^T (+bias)(+res).  mma.sync m16n8k8 tf32.
// SPLIT=1: 3x-tf32 hi/lo decomposition for near-fp32 accuracy (used for Q,K).

__device__ __forceinline__ uint32_t f2tf32(float f) {
    uint32_t r;
    asm("cvt.rna.tf32.f32 %0, %1;" : "=r"(r) : "f"(f));
    return r;
}

__device__ __forceinline__ void mma_tf32(float* c, const uint32_t* a, const uint32_t* b) {
    asm volatile(
        "mma.sync.aligned.m16n8k8.row.col.f32.tf32.tf32.f32 "
        "{%0,%1,%2,%3}, {%4,%5,%6,%7}, {%8,%9}, {%0,%1,%2,%3};\n"
        : "+f"(c[0]), "+f"(c[1]), "+f"(c[2]), "+f"(c[3])
        : "r"(a[0]), "r"(a[1]), "r"(a[2]), "r"(a[3]), "r"(b[0]), "r"(b[1]));
}

#define TBM 128
#define TBN 128
#define TBK 16
#define TS  20        // smem row stride in 32-bit words (pad: conflict-free frag LDS)

template<int SPLIT>
__global__ __launch_bounds__(256) void gemm_tc(
    const float* __restrict__ A, const float* __restrict__ B,
    const float* __restrict__ bias, const float* __restrict__ res,
    float* __restrict__ C, int M, int N, int K)
{
    __shared__ uint32_t As[(1 + SPLIT) * TBM * TS];
    __shared__ uint32_t Bs[(1 + SPLIT) * TBM * TS];

    int tid  = threadIdx.x;
    int lane = tid & 31, warp = tid >> 5;
    int wm = (warp & 1) * 64;        // warp tile origin in M (2 warps down)
    int wn = (warp >> 1) * 32;       // warp tile origin in N (4 warps across)
    int bm = blockIdx.y * TBM, bn = blockIdx.x * TBN;
    int gr = lane >> 2, kq = lane & 3;

    float acc[4][4][4];
    #pragma unroll
    for (int mi = 0; mi < 4; mi++)
        #pragma unroll
        for (int ni = 0; ni < 4; ni++)
            #pragma unroll
            for (int t = 0; t < 4; t++) acc[mi][ni][t] = 0.f;

    const float* Ab = A + (size_t)bm * K;
    const float* Bb = B + (size_t)bn * K;

    for (int k0 = 0; k0 < K; k0 += TBK) {
        // ---- global -> smem (tf32-rounded), [row][k] layout, stride TS ----
        #pragma unroll
        for (int i = 0; i < 2; i++) {
            int idx = tid + i * 256;
            int r = idx >> 2, c4 = (idx & 3) << 2;
            float4 a = *(const float4*)(Ab + (size_t)r * K + k0 + c4);
            uint32_t h0 = f2tf32(a.x), h1 = f2tf32(a.y), h2 = f2tf32(a.z), h3 = f2tf32(a.w);
            uint4 hv; hv.x = h0; hv.y = h1; hv.z = h2; hv.w = h3;
            *(uint4*)&As[r * TS + c4] = hv;
            float4 b = *(const float4*)(Bb + (size_t)r * K + k0 + c4);
            uint32_t g0 = f2tf32(b.x), g1 = f2tf32(b.y), g2 = f2tf32(b.z), g3 = f2tf32(b.w);
            uint4 gv; gv.x = g0; gv.y = g1; gv.z = g2; gv.w = g3;
            *(uint4*)&Bs[r * TS + c4] = gv;
            if (SPLIT) {
                uint4 lv;
                lv.x = f2tf32(a.x - __uint_as_float(h0));
                lv.y = f2tf32(a.y - __uint_as_float(h1));
                lv.z = f2tf32(a.z - __uint_as_float(h2));
                lv.w = f2tf32(a.w - __uint_as_float(h3));
                *(uint4*)&As[TBM * TS + r * TS + c4] = lv;
                uint4 mv;
                mv.x = f2tf32(b.x - __uint_as_float(g0));
                mv.y = f2tf32(b.y - __uint_as_float(g1));
                mv.z = f2tf32(b.z - __uint_as_float(g2));
                mv.w = f2tf32(b.w - __uint_as_float(g3));
                *(uint4*)&Bs[TBM * TS + r * TS + c4] = mv;
            }
        }
        __syncthreads();

        // ---- two k-steps of 8 ----
        #pragma unroll
        for (int ks = 0; ks < TBK; ks += 8) {
            uint32_t af[4][4], bf[4][2];
            #pragma unroll
            for (int mi = 0; mi < 4; mi++) {
                int ra = (wm + 16 * mi + gr) * TS + ks + kq;
                af[mi][0] = As[ra];
                af[mi][1] = As[ra + 8 * TS];
                af[mi][2] = As[ra + 4];
                af[mi][3] = As[ra + 8 * TS + 4];
            }
            #pragma unroll
            for (int ni = 0; ni < 4; ni++) {
                int rb = (wn + 8 * ni + gr) * TS + ks + kq;
                bf[ni][0] = Bs[rb];
                bf[ni][1] = Bs[rb + 4];
            }
            #pragma unroll
            for (int mi = 0; mi < 4; mi++)
                #pragma unroll
                for (int ni = 0; ni < 4; ni++)
                    mma_tf32(acc[mi][ni], af[mi], bf[ni]);

            if (SPLIT) {
                uint32_t al[4][4], bl[4][2];
                #pragma unroll
                for (int mi = 0; mi < 4; mi++) {
                    int ra = TBM * TS + (wm + 16 * mi + gr) * TS + ks + kq;
                    al[mi][0] = As[ra];
                    al[mi][1] = As[ra + 8 * TS];
                    al[mi][2] = As[ra + 4];
                    al[mi][3] = As[ra + 8 * TS + 4];
                }
                #pragma unroll
                for (int ni = 0; ni < 4; ni++) {
                    int rb = TBM * TS + (wn + 8 * ni + gr) * TS + ks + kq;
                    bl[ni][0] = Bs[rb];
                    bl[ni][1] = Bs[rb + 4];
                }
                #pragma unroll
                for (int mi = 0; mi < 4; mi++)
                    #pragma unroll
                    for (int ni = 0; ni < 4; ni++) {
                        mma_tf32(acc[mi][ni], af[mi], bl[ni]);
                        mma_tf32(acc[mi][ni], al[mi], bf[ni]);
                    }
            }
        }
        __syncthreads();
    }

    // ---- epilogue ----
    #pragma unroll
    for (int mi = 0; mi < 4; mi++) {
        int r0 = bm + wm + 16 * mi + gr;
        #pragma unroll
        for (int ni = 0; ni < 4; ni++) {
            int col = bn + wn + 8 * ni + 2 * kq;
            float b0 = 0.f, b1 = 0.f;
            if (bias) { b0 = bias[col]; b1 = bias[col + 1]; }
            float v00 = acc[mi][ni][0] + b0, v01 = acc[mi][ni][1] + b1;
            float v10 = acc[mi][ni][2] + b0, v11 = acc[mi][ni][3] + b1;
            if (res) {
                v00 += res[(size_t)r0 * N + col];
                v01 += res[(size_t)r0 * N + col + 1];
                v10 += res[(size_t)(r0 + 8) * N + col];
                v11 += res[(size_t)(r0 + 8) * N + col + 1];
            }
            float2 lo; lo.x = v00; lo.y = v01;
            float2 hi; hi.x = v10; hi.y = v11;
            *(float2*)&C[(size_t)r0 * N + col] = lo;
            *(float2*)&C[(size_t)(r0 + 8) * N + col] = hi;
        }
    }
}

// ---------------- RoPE (in-place on q and k, [NTOK, D] layout) -------------------
__global__ __launch_bounds__(256) void rope_kernel(float* __restrict__ q, float* __restrict__ k)
{
    int gid = blockIdx.x * 256 + threadIdx.x;   // NTOK * 512 total
    int r   = gid >> 9;                         // token row
    int rem = gid & 511;
    int h   = rem >> 5;
    int d   = rem & 31;
    int s   = r & (Sseq - 1);
    float inv = expf(-(float)d * (9.210340371976184f / 32.0f));
    float ang = (float)s * inv;
    float sn, cs;
    sincosf(ang, &sn, &cs);
    size_t base = (size_t)r * Dm + h * HDd + d;
    float q1 = q[base], q2 = q[base + 32];
    q[base]      = q1 * cs - q2 * sn;
    q[base + 32] = q2 * cs + q1 * sn;
    float k1 = k[base], k2 = k[base + 32];
    k[base]      = k1 * cs - k2 * sn;
    k[base + 32] = k2 * cs + k1 * sn;
}

// ---------------- Sliding-window attention ---------------------------------------
#define QT      64
#define KSPAN   320
#define PSTRIDE 321
#define TSTRIDE 68

__global__ __launch_bounds__(256) void attn_kernel(
    const float* __restrict__ q, const float* __restrict__ k, const float* __restrict__ v,
    float* __restrict__ attn, float* __restrict__ ctx)
{
    extern __shared__ float sm[];
    float* Ps = sm;                              // [64][321] scores -> probs
    float* Qs = sm + QT * PSTRIDE;               // [64 d][68]  (transposed: Qs[d][qi])
    float* Cs = Qs + HDd * TSTRIDE;              // chunk buffer [64][68]

    int blk = blockIdx.x;
    int qt = blk & 15;
    int h  = (blk >> 4) & 15;
    int b  = blk >> 8;
    int q0 = qt * QT;
    int kb = q0 - (WIN - 1);                     // may be negative
    int tid = threadIdx.x;
    int tx = tid & 15, ty = tid >> 4;
    const float scale = 0.125f;                  // 1/sqrt(64)

    for (int idx = tid; idx < QT * HDd; idx += 256) {
        int qi = idx >> 6, d = idx & 63;
        Qs[d * TSTRIDE + qi] = q[(size_t)(b * Sseq + q0 + qi) * Dm + h * HDd + d];
    }

    // ---- phase 1: raw scores over 5 key chunks of 64 ----
    for (int c = 0; c < 5; c++) {
        for (int idx = tid; idx < 64 * HDd; idx += 256) {
            int jj = idx >> 6, d = idx & 63;
            int jg = kb + c * 64 + jj;
            float kv = (jg >= 0 && jg < Sseq)
                       ? k[(size_t)(b * Sseq + jg) * Dm + h * HDd + d] : 0.f;
            Cs[d * TSTRIDE + jj] = kv;
        }
        __syncthreads();
        float acc[4][4] = {{0.f}};
        #pragma unroll 4
        for (int d = 0; d < HDd; d++) {
            float a4[4], b4[4];
            *(float4*)a4 = *(const float4*)&Qs[d * TSTRIDE + ty * 4];
            *(float4*)b4 = *(const float4*)&Cs[d * TSTRIDE + tx * 4];
            #pragma unroll
            for (int i = 0; i < 4; i++)
                #pragma unroll
                for (int jj = 0; jj < 4; jj++)
                    acc[i][jj] += a4[i] * b4[jj];
        }
        #pragma unroll
        for (int i = 0; i < 4; i++)
            #pragma unroll
            for (int jj = 0; jj < 4; jj++)
                Ps[(ty * 4 + i) * PSTRIDE + c * 64 + tx * 4 + jj] = acc[i][jj] * scale;
        __syncthreads();
    }

    // ---- phase 2: softmax per query row (warp per row) + dense write ----
    int warp = tid >> 5, lane = tid & 31;
    for (int qi = warp; qi < QT; qi += 8) {
        int i = q0 + qi;
        int colLo = qi;
        if (-kb > colLo) colLo = -kb;            // enforce j >= 0
        int colHi = qi + (WIN - 1);
        float* prow = Ps + qi * PSTRIDE;
        float m = -1e30f;
        for (int c = lane; c < KSPAN; c += 32)
            if (c >= colLo && c <= colHi) m = fmaxf(m, prow[c]);
        #pragma unroll
        for (int off = 16; off > 0; off >>= 1)
            m = fmaxf(m, __shfl_xor_sync(0xffffffffu, m, off));
        float ssum = 0.f;
        for (int c = lane; c < KSPAN; c += 32) {
            float p = 0.f;
            if (c >= colLo && c <= colHi) p = __expf(prow[c] - m);
            prow[c] = p;
            ssum += p;
        }
        #pragma unroll
        for (int off = 16; off > 0; off >>= 1)
            ssum += __shfl_xor_sync(0xffffffffu, ssum, off);
        float inv = 1.f / ssum;
        float* arow = attn + ((size_t)((b * Hh + h) * Sseq + i)) * Sseq;
        for (int c = lane; c < KSPAN; c += 32) {
            float p = prow[c] * inv;
            prow[c] = p;
            if (c >= colLo && c <= colHi) arow[kb + c] = p;
        }
    }
    __syncthreads();

    // ---- phase 3: ctx = P @ V over 5 value chunks ----
    float acc[4][4] = {{0.f}};
    for (int c = 0; c < 5; c++) {
        for (int idx = tid; idx < 64 * HDd; idx += 256) {
            int jj = idx >> 6, d = idx & 63;
            int jg = kb + c * 64 + jj;
            float vv = (jg >= 0 && jg < Sseq)
                       ? v[(size_t)(b * Sseq + jg) * Dm + h * HDd + d] : 0.f;
            Cs[jj * TSTRIDE + d] = vv;
        }
        __syncthreads();
        #pragma unroll 4
        for (int kk = 0; kk < 64; kk++) {
            float4 vv = *(const float4*)&Cs[kk * TSTRIDE + tx * 4];
            #pragma unroll
            for (int i = 0; i < 4; i++) {
                float p = Ps[(ty * 4 + i) * PSTRIDE + c * 64 + kk];
                acc[i][0] += p * vv.x;
                acc[i][1] += p * vv.y;
                acc[i][2] += p * vv.z;
                acc[i][3] += p * vv.w;
            }
        }
        __syncthreads();
    }
    #pragma unroll
    for (int i = 0; i < 4; i++) {
        int row = b * Sseq + q0 + ty * 4 + i;
        float4 o;
        o.x = acc[i][0]; o.y = acc[i][1]; o.z = acc[i][2]; o.w = acc[i][3];
        *(float4*)&ctx[(size_t)row * Dm + h * HDd + tx * 4] = o;
    }
}

// ---------------- SiLU(gate) * up ------------------------------------------------
__global__ __launch_bounds__(256) void silu_mul_kernel(
    const float* __restrict__ g, const float* __restrict__ u, float* __restrict__ o, int n)
{
    int i = blockIdx.x * 256 + threadIdx.x;
    if (i < n) {
        float a = g[i];
        o[i] = a / (1.f + expf(-a)) * u[i];
    }
}

// ---------------- launch ---------------------------------------------------------
extern "C" void kernel_launch(void* const* d_in, const int* in_sizes, int n_in,
                              void* d_out, int out_size)
{
    const float* x   = (const float*)d_in[0];
    const float* wq  = (const float*)d_in[1];
    const float* bq  = (const float*)d_in[2];
    const float* wk  = (const float*)d_in[3];
    const float* bk  = (const float*)d_in[4];
    const float* wv  = (const float*)d_in[5];
    const float* bv  = (const float*)d_in[6];
    const float* wo  = (const float*)d_in[7];
    const float* bo  = (const float*)d_in[8];
    const float* anw = (const float*)d_in[9];
    const float* fnw = (const float*)d_in[10];
    const float* gw  = (const float*)d_in[11];
    const float* uw  = (const float*)d_in[12];
    const float* dw  = (const float*)d_in[13];

    float* out_x    = (float*)d_out;
    float* out_attn = out_x + (size_t)NTOK * Dm;

    float *h, *qp, *kp, *vp, *ctx, *x1, *h2, *gt, *up, *act;
    cudaGetSymbolAddress((void**)&h,   g_h);
    cudaGetSymbolAddress((void**)&qp,  g_q);
    cudaGetSymbolAddress((void**)&kp,  g_k);
    cudaGetSymbolAddress((void**)&vp,  g_v);
    cudaGetSymbolAddress((void**)&ctx, g_ctx);
    cudaGetSymbolAddress((void**)&x1,  g_x1);
    cudaGetSymbolAddress((void**)&h2,  g_h2);
    cudaGetSymbolAddress((void**)&gt,  g_gate);
    cudaGetSymbolAddress((void**)&up,  g_up);
    cudaGetSymbolAddress((void**)&act, g_act);

    // attn-norm
    rmsnorm_kernel<<<NTOK, 256>>>(x, anw, h);

    // QKV projections (Q,K with 3x-tf32 split for attn-prob accuracy)
    dim3 g1(Dm / TBN, NTOK / TBM);      // (8, 16)
    gemm_tc<1><<<g1, 256>>>(h, wq, bq, nullptr, qp, NTOK, Dm, Dm);
    gemm_tc<1><<<g1, 256>>>(h, wk, bk, nullptr, kp, NTOK, Dm, Dm);
    gemm_tc<0><<<g1, 256>>>(h, wv, bv, nullptr, vp, NTOK, Dm, Dm);

    // RoPE on q and k
    rope_kernel<<<(NTOK * 512) / 256, 256>>>(qp, kp);

    // zero dense attn output, then windowed attention
    cudaMemsetAsync(out_attn, 0, (size_t)Bsz * Hh * Sseq * Sseq * sizeof(float), 0);
    int smemBytes = (QT * PSTRIDE + 2 * 64 * TSTRIDE) * (int)sizeof(float);
    cudaFuncSetAttribute(attn_kernel, cudaFuncAttributeMaxDynamicSharedMemorySize, smemBytes);
    attn_kernel<<<Bsz * Hh * (Sseq / QT), 256, smemBytes>>>(qp, kp, vp, out_attn, ctx);

    // output projection + residual
    gemm_tc<0><<<g1, 256>>>(ctx, wo, bo, x, x1, NTOK, Dm, Dm);

    // ffn-norm
    rmsnorm_kernel<<<NTOK, 256>>>(x1, fnw, h2);

    // FFN
    dim3 g2(FFN_D / TBN, NTOK / TBM);   // (32, 16)
    gemm_tc<0><<<g2, 256>>>(h2, gw, nullptr, nullptr, gt, NTOK, FFN_D, Dm);
    gemm_tc<0><<<g2, 256>>>(h2, uw, nullptr, nullptr, up, NTOK, FFN_D, Dm);
    silu_mul_kernel<<<(NTOK * FFN_D) / 256, 256>>>(gt, up, act, NTOK * FFN_D);
    gemm_tc<0><<<g1, 256>>>(act, dw, nullptr, x1, out_x, NTOK, Dm, FFN_D);
}

// round 8
// speedup vs baseline: 2.1665x; 1.2234x over previous
#include <cuda_runtime.h>
#include <math.h>
#include <stdint.h>

// Problem constants
#define Bsz   2
#define Sseq  1024
#define Dm    1024
#define Hh    16
#define HDd   64
#define WIN   256
#define FFN_D 4096
#define NTOK  (Bsz * Sseq)   // 2048

// ---------------- scratch (no allocation allowed -> __device__ globals) ----------
__device__ float g_h   [NTOK * Dm];
__device__ float g_q   [NTOK * Dm];
__device__ float g_k   [NTOK * Dm];
__device__ float g_v   [NTOK * Dm];
__device__ float g_ctx [NTOK * Dm];
__device__ float g_x1  [NTOK * Dm];
__device__ float g_h2  [NTOK * Dm];
__device__ float g_gate[NTOK * FFN_D];
__device__ float g_up  [NTOK * FFN_D];
__device__ float g_act [NTOK * FFN_D];

// ---------------- RMSNorm: one block per token row ------------------------------
__global__ __launch_bounds__(256) void rmsnorm_kernel(
    const float* __restrict__ x, const float* __restrict__ w, float* __restrict__ o)
{
    int row = blockIdx.x;
    const float* xr = x + (size_t)row * Dm;
    float vals[4];
    float s = 0.f;
    int j = 0;
    for (int i = threadIdx.x; i < Dm; i += 256, j++) {
        float vv = xr[i];
        vals[j] = vv;
        s += vv * vv;
    }
    #pragma unroll
    for (int off = 16; off > 0; off >>= 1)
        s += __shfl_xor_sync(0xffffffffu, s, off);
    __shared__ float red[8];
    if ((threadIdx.x & 31) == 0) red[threadIdx.x >> 5] = s;
    __syncthreads();
    float tot = 0.f;
    #pragma unroll
    for (int i = 0; i < 8; i++) tot += red[i];
    float sc = rsqrtf(tot * (1.0f / Dm) + 1e-6f);
    float* orow = o + (size_t)row * Dm;
    j = 0;
    for (int i = threadIdx.x; i < Dm; i += 256, j++)
        orow[i] = vals[j] * sc * w[i];
}

// ---------------- tf32 tensor-core helpers ---------------------------------------
__device__ __forceinline__ uint32_t f2tf32(float f) {
    uint32_t r;
    asm("cvt.rna.tf32.f32 %0, %1;" : "=r"(r) : "f"(f));
    return r;
}

__device__ __forceinline__ void mma_tf32(float* c, const uint32_t* a, const uint32_t* b) {
    asm volatile(
        "mma.sync.aligned.m16n8k8.row.col.f32.tf32.tf32.f32 "
        "{%0,%1,%2,%3}, {%4,%5,%6,%7}, {%8,%9}, {%0,%1,%2,%3};\n"
        : "+f"(c[0]), "+f"(c[1]), "+f"(c[2]), "+f"(c[3])
        : "r"(a[0]), "r"(a[1]), "r"(a[2]), "r"(a[3]), "r"(b[0]), "r"(b[1]));
}

__device__ __forceinline__ void cp16(uint32_t saddr, const void* g) {
    asm volatile("cp.async.cg.shared.global [%0], [%1], 16;\n" :: "r"(saddr), "l"(g));
}
__device__ __forceinline__ void cp_commit() {
    asm volatile("cp.async.commit_group;\n");
}
template<int N>
__device__ __forceinline__ void cp_wait() {
    asm volatile("cp.async.wait_group %0;\n" :: "n"(N));
}

#define TBM 128
#define TBN 128
#define TBK 16
#define TS  20        // smem row stride in words (conflict-free frag LDS)

// ================= Pipelined plain-tf32 GEMM (cp.async double buffer) ============
// C[M,N] = A[M,K] * B[N,K]^T (+bias)(+res).  fp32 bits fed to HMMA (hw truncation).
__global__ __launch_bounds__(256, 2) void gemm_tc_pipe(
    const float* __restrict__ A, const float* __restrict__ B,
    const float* __restrict__ bias, const float* __restrict__ res,
    float* __restrict__ C, int M, int N, int K)
{
    __shared__ uint32_t As[2][TBM * TS];
    __shared__ uint32_t Bs[2][TBM * TS];

    int tid  = threadIdx.x;
    int lane = tid & 31, warp = tid >> 5;
    int wm = (warp & 1) * 64;
    int wn = (warp >> 1) * 32;
    int bm = blockIdx.y * TBM, bn = blockIdx.x * TBN;
    int gr = lane >> 2, kq = lane & 3;

    float acc[4][4][4];
    #pragma unroll
    for (int mi = 0; mi < 4; mi++)
        #pragma unroll
        for (int ni = 0; ni < 4; ni++)
            #pragma unroll
            for (int t = 0; t < 4; t++) acc[mi][ni][t] = 0.f;

    const float* Ab = A + (size_t)bm * K;
    const float* Bb = B + (size_t)bn * K;

    int r0 = tid >> 2;                 // 0..63
    int c4 = (tid & 3) << 2;           // 0,4,8,12
    uint32_t sA[2], sB[2];
    sA[0] = (uint32_t)__cvta_generic_to_shared(&As[0][0]);
    sA[1] = (uint32_t)__cvta_generic_to_shared(&As[1][0]);
    sB[0] = (uint32_t)__cvta_generic_to_shared(&Bs[0][0]);
    sB[1] = (uint32_t)__cvta_generic_to_shared(&Bs[1][0]);
    uint32_t off0 = (uint32_t)(r0 * TS + c4) * 4u;
    uint32_t off1 = (uint32_t)((r0 + 64) * TS + c4) * 4u;

    int nt = K / TBK;

    // prologue: issue tiles 0 and 1
    #pragma unroll
    for (int p = 0; p < 2; p++) {
        int k0 = p * TBK;
        cp16(sA[p] + off0, Ab + (size_t)r0 * K + k0 + c4);
        cp16(sA[p] + off1, Ab + (size_t)(r0 + 64) * K + k0 + c4);
        cp16(sB[p] + off0, Bb + (size_t)r0 * K + k0 + c4);
        cp16(sB[p] + off1, Bb + (size_t)(r0 + 64) * K + k0 + c4);
        cp_commit();
    }

    for (int t = 0; t < nt; t++) {
        int buf = t & 1;
        cp_wait<1>();
        __syncthreads();

        const uint32_t* Ap = As[buf];
        const uint32_t* Bp = Bs[buf];
        #pragma unroll
        for (int ks = 0; ks < TBK; ks += 8) {
            uint32_t af[4][4], bf[4][2];
            #pragma unroll
            for (int mi = 0; mi < 4; mi++) {
                int ra = (wm + 16 * mi + gr) * TS + ks + kq;
                af[mi][0] = Ap[ra];
                af[mi][1] = Ap[ra + 8 * TS];
                af[mi][2] = Ap[ra + 4];
                af[mi][3] = Ap[ra + 8 * TS + 4];
            }
            #pragma unroll
            for (int ni = 0; ni < 4; ni++) {
                int rb = (wn + 8 * ni + gr) * TS + ks + kq;
                bf[ni][0] = Bp[rb];
                bf[ni][1] = Bp[rb + 4];
            }
            #pragma unroll
            for (int mi = 0; mi < 4; mi++)
                #pragma unroll
                for (int ni = 0; ni < 4; ni++)
                    mma_tf32(acc[mi][ni], af[mi], bf[ni]);
        }
        __syncthreads();

        if (t + 2 < nt) {
            int k0 = (t + 2) * TBK;
            cp16(sA[buf] + off0, Ab + (size_t)r0 * K + k0 + c4);
            cp16(sA[buf] + off1, Ab + (size_t)(r0 + 64) * K + k0 + c4);
            cp16(sB[buf] + off0, Bb + (size_t)r0 * K + k0 + c4);
            cp16(sB[buf] + off1, Bb + (size_t)(r0 + 64) * K + k0 + c4);
        }
        cp_commit();
    }

    // ---- epilogue ----
    #pragma unroll
    for (int mi = 0; mi < 4; mi++) {
        int rr = bm + wm + 16 * mi + gr;
        #pragma unroll
        for (int ni = 0; ni < 4; ni++) {
            int col = bn + wn + 8 * ni + 2 * kq;
            float b0 = 0.f, b1 = 0.f;
            if (bias) { b0 = bias[col]; b1 = bias[col + 1]; }
            float v00 = acc[mi][ni][0] + b0, v01 = acc[mi][ni][1] + b1;
            float v10 = acc[mi][ni][2] + b0, v11 = acc[mi][ni][3] + b1;
            if (res) {
                v00 += res[(size_t)rr * N + col];
                v01 += res[(size_t)rr * N + col + 1];
                v10 += res[(size_t)(rr + 8) * N + col];
                v11 += res[(size_t)(rr + 8) * N + col + 1];
            }
            float2 lo; lo.x = v00; lo.y = v01;
            float2 hi; hi.x = v10; hi.y = v11;
            *(float2*)&C[(size_t)rr * N + col] = lo;
            *(float2*)&C[(size_t)(rr + 8) * N + col] = hi;
        }
    }
}

// ================= 3x-tf32 split GEMM (Q,K — near-fp32, reg-prefetched) ==========
__global__ __launch_bounds__(256) void gemm_tc_split(
    const float* __restrict__ A, const float* __restrict__ B,
    const float* __restrict__ bias, const float* __restrict__ res,
    float* __restrict__ C, int M, int N, int K)
{
    __shared__ uint32_t As[2 * TBM * TS];
    __shared__ uint32_t Bs[2 * TBM * TS];

    int tid  = threadIdx.x;
    int lane = tid & 31, warp = tid >> 5;
    int wm = (warp & 1) * 64;
    int wn = (warp >> 1) * 32;
    int bm = blockIdx.y * TBM, bn = blockIdx.x * TBN;
    int gr = lane >> 2, kq = lane & 3;

    float acc[4][4][4];
    #pragma unroll
    for (int mi = 0; mi < 4; mi++)
        #pragma unroll
        for (int ni = 0; ni < 4; ni++)
            #pragma unroll
            for (int t = 0; t < 4; t++) acc[mi][ni][t] = 0.f;

    const float* Ab = A + (size_t)bm * K;
    const float* Bb = B + (size_t)bn * K;

    int r0 = tid >> 2;
    int c4 = (tid & 3) << 2;

    // prefetch tile 0
    float4 pa0 = *(const float4*)(Ab + (size_t)r0 * K + c4);
    float4 pa1 = *(const float4*)(Ab + (size_t)(r0 + 64) * K + c4);
    float4 pb0 = *(const float4*)(Bb + (size_t)r0 * K + c4);
    float4 pb1 = *(const float4*)(Bb + (size_t)(r0 + 64) * K + c4);

    int nt = K / TBK;
    for (int t = 0; t < nt; t++) {
        // store hi/lo (cvt) for current tile
        {
            float4 v;
            uint32_t h0, h1, h2, h3;
            v = pa0;
            h0 = f2tf32(v.x); h1 = f2tf32(v.y); h2 = f2tf32(v.z); h3 = f2tf32(v.w);
            { uint4 u; u.x = h0; u.y = h1; u.z = h2; u.w = h3;
              *(uint4*)&As[r0 * TS + c4] = u; }
            { uint4 u;
              u.x = f2tf32(v.x - __uint_as_float(h0));
              u.y = f2tf32(v.y - __uint_as_float(h1));
              u.z = f2tf32(v.z - __uint_as_float(h2));
              u.w = f2tf32(v.w - __uint_as_float(h3));
              *(uint4*)&As[TBM * TS + r0 * TS + c4] = u; }
            v = pa1;
            h0 = f2tf32(v.x); h1 = f2tf32(v.y); h2 = f2tf32(v.z); h3 = f2tf32(v.w);
            { uint4 u; u.x = h0; u.y = h1; u.z = h2; u.w = h3;
              *(uint4*)&As[(r0 + 64) * TS + c4] = u; }
            { uint4 u;
              u.x = f2tf32(v.x - __uint_as_float(h0));
              u.y = f2tf32(v.y - __uint_as_float(h1));
              u.z = f2tf32(v.z - __uint_as_float(h2));
              u.w = f2tf32(v.w - __uint_as_float(h3));
              *(uint4*)&As[TBM * TS + (r0 + 64) * TS + c4] = u; }
            v = pb0;
            h0 = f2tf32(v.x); h1 = f2tf32(v.y); h2 = f2tf32(v.z); h3 = f2tf32(v.w);
            { uint4 u; u.x = h0; u.y = h1; u.z = h2; u.w = h3;
              *(uint4*)&Bs[r0 * TS + c4] = u; }
            { uint4 u;
              u.x = f2tf32(v.x - __uint_as_float(h0));
              u.y = f2tf32(v.y - __uint_as_float(h1));
              u.z = f2tf32(v.z - __uint_as_float(h2));
              u.w = f2tf32(v.w - __uint_as_float(h3));
              *(uint4*)&Bs[TBM * TS + r0 * TS + c4] = u; }
            v = pb1;
            h0 = f2tf32(v.x); h1 = f2tf32(v.y); h2 = f2tf32(v.z); h3 = f2tf32(v.w);
            { uint4 u; u.x = h0; u.y = h1; u.z = h2; u.w = h3;
              *(uint4*)&Bs[(r0 + 64) * TS + c4] = u; }
            { uint4 u;
              u.x = f2tf32(v.x - __uint_as_float(h0));
              u.y = f2tf32(v.y - __uint_as_float(h1));
              u.z = f2tf32(v.z - __uint_as_float(h2));
              u.w = f2tf32(v.w - __uint_as_float(h3));
              *(uint4*)&Bs[TBM * TS + (r0 + 64) * TS + c4] = u; }
        }
        __syncthreads();

        // prefetch next tile (LDGs overlap with MMA below)
        if (t + 1 < nt) {
            int k0 = (t + 1) * TBK;
            pa0 = *(const float4*)(Ab + (size_t)r0 * K + k0 + c4);
            pa1 = *(const float4*)(Ab + (size_t)(r0 + 64) * K + k0 + c4);
            pb0 = *(const float4*)(Bb + (size_t)r0 * K + k0 + c4);
            pb1 = *(const float4*)(Bb + (size_t)(r0 + 64) * K + k0 + c4);
        }

        #pragma unroll
        for (int ks = 0; ks < TBK; ks += 8) {
            uint32_t af[4][4], bf[4][2], al[4][4], bl[4][2];
            #pragma unroll
            for (int mi = 0; mi < 4; mi++) {
                int ra = (wm + 16 * mi + gr) * TS + ks + kq;
                af[mi][0] = As[ra];
                af[mi][1] = As[ra + 8 * TS];
                af[mi][2] = As[ra + 4];
                af[mi][3] = As[ra + 8 * TS + 4];
                al[mi][0] = As[TBM * TS + ra];
                al[mi][1] = As[TBM * TS + ra + 8 * TS];
                al[mi][2] = As[TBM * TS + ra + 4];
                al[mi][3] = As[TBM * TS + ra + 8 * TS + 4];
            }
            #pragma unroll
            for (int ni = 0; ni < 4; ni++) {
                int rb = (wn + 8 * ni + gr) * TS + ks + kq;
                bf[ni][0] = Bs[rb];
                bf[ni][1] = Bs[rb + 4];
                bl[ni][0] = Bs[TBM * TS + rb];
                bl[ni][1] = Bs[TBM * TS + rb + 4];
            }
            #pragma unroll
            for (int mi = 0; mi < 4; mi++)
                #pragma unroll
                for (int ni = 0; ni < 4; ni++) {
                    mma_tf32(acc[mi][ni], af[mi], bf[ni]);
                    mma_tf32(acc[mi][ni], af[mi], bl[ni]);
                    mma_tf32(acc[mi][ni], al[mi], bf[ni]);
                }
        }
        __syncthreads();
    }

    #pragma unroll
    for (int mi = 0; mi < 4; mi++) {
        int rr = bm + wm + 16 * mi + gr;
        #pragma unroll
        for (int ni = 0; ni < 4; ni++) {
            int col = bn + wn + 8 * ni + 2 * kq;
            float b0 = 0.f, b1 = 0.f;
            if (bias) { b0 = bias[col]; b1 = bias[col + 1]; }
            float v00 = acc[mi][ni][0] + b0, v01 = acc[mi][ni][1] + b1;
            float v10 = acc[mi][ni][2] + b0, v11 = acc[mi][ni][3] + b1;
            if (res) {
                v00 += res[(size_t)rr * N + col];
                v01 += res[(size_t)rr * N + col + 1];
                v10 += res[(size_t)(rr + 8) * N + col];
                v11 += res[(size_t)(rr + 8) * N + col + 1];
            }
            float2 lo; lo.x = v00; lo.y = v01;
            float2 hi; hi.x = v10; hi.y = v11;
            *(float2*)&C[(size_t)rr * N + col] = lo;
            *(float2*)&C[(size_t)(rr + 8) * N + col] = hi;
        }
    }
}

// ---------------- RoPE (in-place on q and k, [NTOK, D] layout) -------------------
__global__ __launch_bounds__(256) void rope_kernel(float* __restrict__ q, float* __restrict__ k)
{
    int gid = blockIdx.x * 256 + threadIdx.x;   // NTOK * 512 total
    int r   = gid >> 9;
    int rem = gid & 511;
    int h   = rem >> 5;
    int d   = rem & 31;
    int s   = r & (Sseq - 1);
    float inv = expf(-(float)d * (9.210340371976184f / 32.0f));
    float ang = (float)s * inv;
    float sn, cs;
    sincosf(ang, &sn, &cs);
    size_t base = (size_t)r * Dm + h * HDd + d;
    float q1 = q[base], q2 = q[base + 32];
    q[base]      = q1 * cs - q2 * sn;
    q[base + 32] = q2 * cs + q1 * sn;
    float k1 = k[base], k2 = k[base + 32];
    k[base]      = k1 * cs - k2 * sn;
    k[base + 32] = k2 * cs + k1 * sn;
}

// ---------------- Sliding-window attention ---------------------------------------
#define QT      64
#define KSPAN   320
#define PSTRIDE 321
#define TSTRIDE 68

__global__ __launch_bounds__(256) void attn_kernel(
    const float* __restrict__ q, const float* __restrict__ k, const float* __restrict__ v,
    float* __restrict__ attn, float* __restrict__ ctx)
{
    extern __shared__ float sm[];
    float* Ps = sm;                              // [64][321]
    float* Qs = sm + QT * PSTRIDE;               // [64 d][68]
    float* Cs = Qs + HDd * TSTRIDE;              // [64][68]

    int blk = blockIdx.x;
    int qt = blk & 15;
    int h  = (blk >> 4) & 15;
    int b  = blk >> 8;
    int q0 = qt * QT;
    int kb = q0 - (WIN - 1);
    int tid = threadIdx.x;
    int tx = tid & 15, ty = tid >> 4;
    const float scale = 0.125f;

    for (int idx = tid; idx < QT * HDd; idx += 256) {
        int qi = idx >> 6, d = idx & 63;
        Qs[d * TSTRIDE + qi] = q[(size_t)(b * Sseq + q0 + qi) * Dm + h * HDd + d];
    }

    for (int c = 0; c < 5; c++) {
        for (int idx = tid; idx < 64 * HDd; idx += 256) {
            int jj = idx >> 6, d = idx & 63;
            int jg = kb + c * 64 + jj;
            float kv = (jg >= 0 && jg < Sseq)
                       ? k[(size_t)(b * Sseq + jg) * Dm + h * HDd + d] : 0.f;
            Cs[d * TSTRIDE + jj] = kv;
        }
        __syncthreads();
        float acc[4][4] = {{0.f}};
        #pragma unroll 4
        for (int d = 0; d < HDd; d++) {
            float a4[4], b4[4];
            *(float4*)a4 = *(const float4*)&Qs[d * TSTRIDE + ty * 4];
            *(float4*)b4 = *(const float4*)&Cs[d * TSTRIDE + tx * 4];
            #pragma unroll
            for (int i = 0; i < 4; i++)
                #pragma unroll
                for (int jj = 0; jj < 4; jj++)
                    acc[i][jj] += a4[i] * b4[jj];
        }
        #pragma unroll
        for (int i = 0; i < 4; i++)
            #pragma unroll
            for (int jj = 0; jj < 4; jj++)
                Ps[(ty * 4 + i) * PSTRIDE + c * 64 + tx * 4 + jj] = acc[i][jj] * scale;
        __syncthreads();
    }

    int warp = tid >> 5, lane = tid & 31;
    for (int qi = warp; qi < QT; qi += 8) {
        int i = q0 + qi;
        int colLo = qi;
        if (-kb > colLo) colLo = -kb;
        int colHi = qi + (WIN - 1);
        float* prow = Ps + qi * PSTRIDE;
        float m = -1e30f;
        for (int c = lane; c < KSPAN; c += 32)
            if (c >= colLo && c <= colHi) m = fmaxf(m, prow[c]);
        #pragma unroll
        for (int off = 16; off > 0; off >>= 1)
            m = fmaxf(m, __shfl_xor_sync(0xffffffffu, m, off));
        float ssum = 0.f;
        for (int c = lane; c < KSPAN; c += 32) {
            float p = 0.f;
            if (c >= colLo && c <= colHi) p = __expf(prow[c] - m);
            prow[c] = p;
            ssum += p;
        }
        #pragma unroll
        for (int off = 16; off > 0; off >>= 1)
            ssum += __shfl_xor_sync(0xffffffffu, ssum, off);
        float inv = 1.f / ssum;
        float* arow = attn + ((size_t)((b * Hh + h) * Sseq + i)) * Sseq;
        for (int c = lane; c < KSPAN; c += 32) {
            float p = prow[c] * inv;
            prow[c] = p;
            if (c >= colLo && c <= colHi) arow[kb + c] = p;
        }
    }
    __syncthreads();

    float acc[4][4] = {{0.f}};
    for (int c = 0; c < 5; c++) {
        for (int idx = tid; idx < 64 * HDd; idx += 256) {
            int jj = idx >> 6, d = idx & 63;
            int jg = kb + c * 64 + jj;
            float vv = (jg >= 0 && jg < Sseq)
                       ? v[(size_t)(b * Sseq + jg) * Dm + h * HDd + d] : 0.f;
            Cs[jj * TSTRIDE + d] = vv;
        }
        __syncthreads();
        #pragma unroll 4
        for (int kk = 0; kk < 64; kk++) {
            float4 vv = *(const float4*)&Cs[kk * TSTRIDE + tx * 4];
            #pragma unroll
            for (int i = 0; i < 4; i++) {
                float p = Ps[(ty * 4 + i) * PSTRIDE + c * 64 + kk];
                acc[i][0] += p * vv.x;
                acc[i][1] += p * vv.y;
                acc[i][2] += p * vv.z;
                acc[i][3] += p * vv.w;
            }
        }
        __syncthreads();
    }
    #pragma unroll
    for (int i = 0; i < 4; i++) {
        int row = b * Sseq + q0 + ty * 4 + i;
        float4 o;
        o.x = acc[i][0]; o.y = acc[i][1]; o.z = acc[i][2]; o.w = acc[i][3];
        *(float4*)&ctx[(size_t)row * Dm + h * HDd + tx * 4] = o;
    }
}

// ---------------- SiLU(gate) * up ------------------------------------------------
__global__ __launch_bounds__(256) void silu_mul_kernel(
    const float* __restrict__ g, const float* __restrict__ u, float* __restrict__ o, int n)
{
    int i = blockIdx.x * 256 + threadIdx.x;
    if (i < n) {
        float a = g[i];
        o[i] = a / (1.f + expf(-a)) * u[i];
    }
}

// ---------------- launch ---------------------------------------------------------
extern "C" void kernel_launch(void* const* d_in, const int* in_sizes, int n_in,
                              void* d_out, int out_size)
{
    const float* x   = (const float*)d_in[0];
    const float* wq  = (const float*)d_in[1];
    const float* bq  = (const float*)d_in[2];
    const float* wk  = (const float*)d_in[3];
    const float* bk  = (const float*)d_in[4];
    const float* wv  = (const float*)d_in[5];
    const float* bv  = (const float*)d_in[6];
    const float* wo  = (const float*)d_in[7];
    const float* bo  = (const float*)d_in[8];
    const float* anw = (const float*)d_in[9];
    const float* fnw = (const float*)d_in[10];
    const float* gw  = (const float*)d_in[11];
    const float* uw  = (const float*)d_in[12];
    const float* dw  = (const float*)d_in[13];

    float* out_x    = (float*)d_out;
    float* out_attn = out_x + (size_t)NTOK * Dm;

    float *h, *qp, *kp, *vp, *ctx, *x1, *h2, *gt, *up, *act;
    cudaGetSymbolAddress((void**)&h,   g_h);
    cudaGetSymbolAddress((void**)&qp,  g_q);
    cudaGetSymbolAddress((void**)&kp,  g_k);
    cudaGetSymbolAddress((void**)&vp,  g_v);
    cudaGetSymbolAddress((void**)&ctx, g_ctx);
    cudaGetSymbolAddress((void**)&x1,  g_x1);
    cudaGetSymbolAddress((void**)&h2,  g_h2);
    cudaGetSymbolAddress((void**)&gt,  g_gate);
    cudaGetSymbolAddress((void**)&up,  g_up);
    cudaGetSymbolAddress((void**)&act, g_act);

    // attn-norm
    rmsnorm_kernel<<<NTOK, 256>>>(x, anw, h);

    // QKV projections (Q,K with 3x-tf32 split for attn-prob accuracy)
    dim3 g1(Dm / TBN, NTOK / TBM);      // (8, 16)
    gemm_tc_split<<<g1, 256>>>(h, wq, bq, nullptr, qp, NTOK, Dm, Dm);
    gemm_tc_split<<<g1, 256>>>(h, wk, bk, nullptr, kp, NTOK, Dm, Dm);
    gemm_tc_pipe <<<g1, 256>>>(h, wv, bv, nullptr, vp, NTOK, Dm, Dm);

    // RoPE on q and k
    rope_kernel<<<(NTOK * 512) / 256, 256>>>(qp, kp);

    // zero dense attn output, then windowed attention
    cudaMemsetAsync(out_attn, 0, (size_t)Bsz * Hh * Sseq * Sseq * sizeof(float), 0);
    int smemBytes = (QT * PSTRIDE + 2 * 64 * TSTRIDE) * (int)sizeof(float);
    cudaFuncSetAttribute(attn_kernel, cudaFuncAttributeMaxDynamicSharedMemorySize, smemBytes);
    attn_kernel<<<Bsz * Hh * (Sseq / QT), 256, smemBytes>>>(qp, kp, vp, out_attn, ctx);

    // output projection + residual
    gemm_tc_pipe<<<g1, 256>>>(ctx, wo, bo, x, x1, NTOK, Dm, Dm);

    // ffn-norm
    rmsnorm_kernel<<<NTOK, 256>>>(x1, fnw, h2);

    // FFN
    dim3 g2(FFN_D / TBN, NTOK / TBM);   // (32, 16)
    gemm_tc_pipe<<<g2, 256>>>(h2, gw, nullptr, nullptr, gt, NTOK, FFN_D, Dm);
    gemm_tc_pipe<<<g2, 256>>>(h2, uw, nullptr, nullptr, up, NTOK, FFN_D, Dm);
    silu_mul_kernel<<<(NTOK * FFN_D) / 256, 256>>>(gt, up, act, NTOK * FFN_D);
    gemm_tc_pipe<<<g1, 256>>>(act, dw, nullptr, x1, out_x, NTOK, Dm, FFN_D);
}

// round 11
// speedup vs baseline: 2.3277x; 1.0744x over previous
#include <cuda_runtime.h>
#include <math.h>
#include <stdint.h>

// Problem constants
#define Bsz   2
#define Sseq  1024
#define Dm    1024
#define Hh    16
#define HDd   64
#define WIN   256
#define FFN_D 4096
#define NTOK  (Bsz * Sseq)   // 2048

// ---------------- scratch (no allocation allowed -> __device__ globals) ----------
__device__ float g_h   [NTOK * Dm];
__device__ float g_q   [NTOK * Dm];
__device__ float g_k   [NTOK * Dm];
__device__ float g_v   [NTOK * Dm];
__device__ float g_ctx [NTOK * Dm];
__device__ float g_x1  [NTOK * Dm];
__device__ float g_h2  [NTOK * Dm];
__device__ float g_gate[NTOK * FFN_D];
__device__ float g_up  [NTOK * FFN_D];
__device__ float g_act [NTOK * FFN_D];
// pre-rounded (tf32-rna) weights
__device__ float g_wv [Dm * Dm];
__device__ float g_wo [Dm * Dm];
__device__ float g_gw [FFN_D * Dm];
__device__ float g_uw [FFN_D * Dm];
__device__ float g_dw [Dm * FFN_D];

// ---------------- helpers --------------------------------------------------------
__device__ __forceinline__ uint32_t f2tf32(float f) {
    uint32_t r;
    asm("cvt.rna.tf32.f32 %0, %1;" : "=r"(r) : "f"(f));
    return r;
}
__device__ __forceinline__ float roundtf(float f) { return __uint_as_float(f2tf32(f)); }

__device__ __forceinline__ void mma_tf32(float* c, const uint32_t* a, const uint32_t* b) {
    asm volatile(
        "mma.sync.aligned.m16n8k8.row.col.f32.tf32.tf32.f32 "
        "{%0,%1,%2,%3}, {%4,%5,%6,%7}, {%8,%9}, {%0,%1,%2,%3};\n"
        : "+f"(c[0]), "+f"(c[1]), "+f"(c[2]), "+f"(c[3])
        : "r"(a[0]), "r"(a[1]), "r"(a[2]), "r"(a[3]), "r"(b[0]), "r"(b[1]));
}
__device__ __forceinline__ void mma_bf16(float* c, const uint32_t* a, const uint32_t* b) {
    asm volatile(
        "mma.sync.aligned.m16n8k16.row.col.f32.bf16.bf16.f32 "
        "{%0,%1,%2,%3}, {%4,%5,%6,%7}, {%8,%9}, {%0,%1,%2,%3};\n"
        : "+f"(c[0]), "+f"(c[1]), "+f"(c[2]), "+f"(c[3])
        : "r"(a[0]), "r"(a[1]), "r"(a[2]), "r"(a[3]), "r"(b[0]), "r"(b[1]));
}

__device__ __forceinline__ uint32_t packbf(float lo, float hi) {
    uint32_t r;
    asm("cvt.rn.bf16x2.f32 %0, %1, %2;" : "=r"(r) : "f"(hi), "f"(lo));
    return r;
}
// split (x,y) into packed bf16x2 hi + lo (a = hi + lo to ~2^-18)
__device__ __forceinline__ void split2(float x, float y, uint32_t& hi, uint32_t& lo) {
    hi = packbf(x, y);
    float hx = __uint_as_float(hi << 16);
    float hy = __uint_as_float(hi & 0xFFFF0000u);
    lo = packbf(x - hx, y - hy);
}

__device__ __forceinline__ void cp16(uint32_t saddr, const void* g) {
    asm volatile("cp.async.cg.shared.global [%0], [%1], 16;\n" :: "r"(saddr), "l"(g));
}
__device__ __forceinline__ void cp_commit() {
    asm volatile("cp.async.commit_group;\n");
}
template<int N>
__device__ __forceinline__ void cp_wait() {
    asm volatile("cp.async.wait_group %0;\n" :: "n"(N));
}

// ---------------- weight rounding (tf32-rna) -------------------------------------
__global__ __launch_bounds__(256) void round_tf32_kernel(
    const float4* __restrict__ in, float4* __restrict__ out, int n4)
{
    int i = blockIdx.x * 256 + threadIdx.x;
    if (i < n4) {
        float4 v = in[i];
        v.x = roundtf(v.x); v.y = roundtf(v.y);
        v.z = roundtf(v.z); v.w = roundtf(v.w);
        out[i] = v;
    }
}

// ---------------- RMSNorm: one block per token row ------------------------------
__global__ __launch_bounds__(256) void rmsnorm_kernel(
    const float* __restrict__ x, const float* __restrict__ w, float* __restrict__ o,
    int doRound)
{
    int row = blockIdx.x;
    const float* xr = x + (size_t)row * Dm;
    float vals[4];
    float s = 0.f;
    int j = 0;
    for (int i = threadIdx.x; i < Dm; i += 256, j++) {
        float vv = xr[i];
        vals[j] = vv;
        s += vv * vv;
    }
    #pragma unroll
    for (int off = 16; off > 0; off >>= 1)
        s += __shfl_xor_sync(0xffffffffu, s, off);
    __shared__ float red[8];
    if ((threadIdx.x & 31) == 0) red[threadIdx.x >> 5] = s;
    __syncthreads();
    float tot = 0.f;
    #pragma unroll
    for (int i = 0; i < 8; i++) tot += red[i];
    float sc = rsqrtf(tot * (1.0f / Dm) + 1e-6f);
    float* orow = o + (size_t)row * Dm;
    j = 0;
    for (int i = threadIdx.x; i < Dm; i += 256, j++) {
        float r = vals[j] * sc * w[i];
        orow[i] = doRound ? roundtf(r) : r;
    }
}

#define TBM 128
#define TBN 128
#define TBK 16
#define TS  20         // smem row stride in words
#define NSTG 4         // pipeline stages
#define STGW (TBM * TS)          // words per operand per stage
#define SMEM_GEMM (NSTG * 2 * STGW * 4)  // bytes

// ================= 4-stage pipelined tf32 GEMM ===================================
// C[M,N] = A[M,K]*B[N,K]^T (+bias)(+res). Operands pre-rounded to tf32-rna.
__global__ __launch_bounds__(256, 2) void gemm_tc_pipe(
    const float* __restrict__ A, const float* __restrict__ B,
    const float* __restrict__ bias, const float* __restrict__ res,
    float* __restrict__ C, int M, int N, int K)
{
    extern __shared__ uint32_t smem_u[];
    uint32_t* As = smem_u;                 // [NSTG][STGW]
    uint32_t* Bs = smem_u + NSTG * STGW;   // [NSTG][STGW]

    int tid  = threadIdx.x;
    int lane = tid & 31, warp = tid >> 5;
    int wm = (warp & 1) * 64;
    int wn = (warp >> 1) * 32;
    int bm = blockIdx.y * TBM, bn = blockIdx.x * TBN;
    int gr = lane >> 2, kq = lane & 3;

    float acc[4][4][4];
    #pragma unroll
    for (int mi = 0; mi < 4; mi++)
        #pragma unroll
        for (int ni = 0; ni < 4; ni++)
            #pragma unroll
            for (int t = 0; t < 4; t++) acc[mi][ni][t] = 0.f;

    const float* Ab = A + (size_t)bm * K;
    const float* Bb = B + (size_t)bn * K;

    int r0 = tid >> 2;                 // 0..63
    int c4 = (tid & 3) << 2;           // 0,4,8,12
    uint32_t sAb = (uint32_t)__cvta_generic_to_shared(As);
    uint32_t sBb = (uint32_t)__cvta_generic_to_shared(Bs);
    uint32_t off0 = (uint32_t)(r0 * TS + c4) * 4u;
    uint32_t off1 = (uint32_t)((r0 + 64) * TS + c4) * 4u;

    int nt = K / TBK;

    // prologue: tiles 0..NSTG-2
    #pragma unroll
    for (int p = 0; p < NSTG - 1; p++) {
        int k0 = p * TBK;
        uint32_t sa = sAb + p * STGW * 4, sb = sBb + p * STGW * 4;
        cp16(sa + off0, Ab + (size_t)r0 * K + k0 + c4);
        cp16(sa + off1, Ab + (size_t)(r0 + 64) * K + k0 + c4);
        cp16(sb + off0, Bb + (size_t)r0 * K + k0 + c4);
        cp16(sb + off1, Bb + (size_t)(r0 + 64) * K + k0 + c4);
        cp_commit();
    }

    for (int t = 0; t < nt; t++) {
        int buf = t & (NSTG - 1);
        cp_wait<NSTG - 2>();
        __syncthreads();

        // issue tile t+NSTG-1 into buffer freed at iteration t-1
        int tn = t + NSTG - 1;
        if (tn < nt) {
            int nb = tn & (NSTG - 1);
            int k0 = tn * TBK;
            uint32_t sa = sAb + nb * STGW * 4, sb = sBb + nb * STGW * 4;
            cp16(sa + off0, Ab + (size_t)r0 * K + k0 + c4);
            cp16(sa + off1, Ab + (size_t)(r0 + 64) * K + k0 + c4);
            cp16(sb + off0, Bb + (size_t)r0 * K + k0 + c4);
            cp16(sb + off1, Bb + (size_t)(r0 + 64) * K + k0 + c4);
        }
        cp_commit();

        const uint32_t* Ap = As + buf * STGW;
        const uint32_t* Bp = Bs + buf * STGW;
        #pragma unroll
        for (int ks = 0; ks < TBK; ks += 8) {
            uint32_t af[4][4], bf[4][2];
            #pragma unroll
            for (int mi = 0; mi < 4; mi++) {
                int ra = (wm + 16 * mi + gr) * TS + ks + kq;
                af[mi][0] = Ap[ra];
                af[mi][1] = Ap[ra + 8 * TS];
                af[mi][2] = Ap[ra + 4];
                af[mi][3] = Ap[ra + 8 * TS + 4];
            }
            #pragma unroll
            for (int ni = 0; ni < 4; ni++) {
                int rb = (wn + 8 * ni + gr) * TS + ks + kq;
                bf[ni][0] = Bp[rb];
                bf[ni][1] = Bp[rb + 4];
            }
            #pragma unroll
            for (int mi = 0; mi < 4; mi++)
                #pragma unroll
                for (int ni = 0; ni < 4; ni++)
                    mma_tf32(acc[mi][ni], af[mi], bf[ni]);
        }
    }

    __syncthreads();
    // ---- epilogue ----
    #pragma unroll
    for (int mi = 0; mi < 4; mi++) {
        int rr = bm + wm + 16 * mi + gr;
        #pragma unroll
        for (int ni = 0; ni < 4; ni++) {
            int col = bn + wn + 8 * ni + 2 * kq;
            float b0 = 0.f, b1 = 0.f;
            if (bias) { b0 = bias[col]; b1 = bias[col + 1]; }
            float v00 = acc[mi][ni][0] + b0, v01 = acc[mi][ni][1] + b1;
            float v10 = acc[mi][ni][2] + b0, v11 = acc[mi][ni][3] + b1;
            if (res) {
                v00 += res[(size_t)rr * N + col];
                v01 += res[(size_t)rr * N + col + 1];
                v10 += res[(size_t)(rr + 8) * N + col];
                v11 += res[(size_t)(rr + 8) * N + col + 1];
            }
            float2 lo; lo.x = v00; lo.y = v01;
            float2 hi; hi.x = v10; hi.y = v11;
            *(float2*)&C[(size_t)rr * N + col] = lo;
            *(float2*)&C[(size_t)(rr + 8) * N + col] = hi;
        }
    }
}

// ================= 4-stage pipelined bf16 3-term split GEMM (Q,K) ================
// Near-fp32 accuracy: a*b ~= ah*bh + ah*bl + al*bh  (error ~2^-18 rel).
__global__ __launch_bounds__(256) void gemm_bf16_split(
    const float* __restrict__ A, const float* __restrict__ B,
    const float* __restrict__ bias, const float* __restrict__ res,
    float* __restrict__ C, int M, int N, int K)
{
    extern __shared__ uint32_t smem_u[];
    uint32_t* As = smem_u;
    uint32_t* Bs = smem_u + NSTG * STGW;

    int tid  = threadIdx.x;
    int lane = tid & 31, warp = tid >> 5;
    int wm = (warp & 1) * 64;
    int wn = (warp >> 1) * 32;
    int bm = blockIdx.y * TBM, bn = blockIdx.x * TBN;
    int gr = lane >> 2, kq = lane & 3;

    float acc[4][4][4];
    #pragma unroll
    for (int mi = 0; mi < 4; mi++)
        #pragma unroll
        for (int ni = 0; ni < 4; ni++)
            #pragma unroll
            for (int t = 0; t < 4; t++) acc[mi][ni][t] = 0.f;

    const float* Ab = A + (size_t)bm * K;
    const float* Bb = B + (size_t)bn * K;

    int r0 = tid >> 2;
    int c4 = (tid & 3) << 2;
    uint32_t sAb = (uint32_t)__cvta_generic_to_shared(As);
    uint32_t sBb = (uint32_t)__cvta_generic_to_shared(Bs);
    uint32_t off0 = (uint32_t)(r0 * TS + c4) * 4u;
    uint32_t off1 = (uint32_t)((r0 + 64) * TS + c4) * 4u;

    int nt = K / TBK;

    #pragma unroll
    for (int p = 0; p < NSTG - 1; p++) {
        int k0 = p * TBK;
        uint32_t sa = sAb + p * STGW * 4, sb = sBb + p * STGW * 4;
        cp16(sa + off0, Ab + (size_t)r0 * K + k0 + c4);
        cp16(sa + off1, Ab + (size_t)(r0 + 64) * K + k0 + c4);
        cp16(sb + off0, Bb + (size_t)r0 * K + k0 + c4);
        cp16(sb + off1, Bb + (size_t)(r0 + 64) * K + k0 + c4);
        cp_commit();
    }

    for (int t = 0; t < nt; t++) {
        int buf = t & (NSTG - 1);
        cp_wait<NSTG - 2>();
        __syncthreads();

        int tn = t + NSTG - 1;
        if (tn < nt) {
            int nb = tn & (NSTG - 1);
            int k0 = tn * TBK;
            uint32_t sa = sAb + nb * STGW * 4, sb = sBb + nb * STGW * 4;
            cp16(sa + off0, Ab + (size_t)r0 * K + k0 + c4);
            cp16(sa + off1, Ab + (size_t)(r0 + 64) * K + k0 + c4);
            cp16(sb + off0, Bb + (size_t)r0 * K + k0 + c4);
            cp16(sb + off1, Bb + (size_t)(r0 + 64) * K + k0 + c4);
        }
        cp_commit();

        const float* Apf = (const float*)(As + buf * STGW);
        const float* Bpf = (const float*)(Bs + buf * STGW);

        // one k16 step per tile
        uint32_t ah[4][4], al[4][4], bh[4][2], bl[4][2];
        #pragma unroll
        for (int mi = 0; mi < 4; mi++) {
            int rbase = (wm + 16 * mi + gr) * TS + 2 * kq;
            float2 p0 = *(const float2*)&Apf[rbase];
            float2 p1 = *(const float2*)&Apf[rbase + 8 * TS];
            float2 p2 = *(const float2*)&Apf[rbase + 8];
            float2 p3 = *(const float2*)&Apf[rbase + 8 * TS + 8];
            split2(p0.x, p0.y, ah[mi][0], al[mi][0]);
            split2(p1.x, p1.y, ah[mi][1], al[mi][1]);
            split2(p2.x, p2.y, ah[mi][2], al[mi][2]);
            split2(p3.x, p3.y, ah[mi][3], al[mi][3]);
        }
        #pragma unroll
        for (int ni = 0; ni < 4; ni++) {
            int nb2 = (wn + 8 * ni + gr) * TS + 2 * kq;
            float2 q0 = *(const float2*)&Bpf[nb2];
            float2 q1 = *(const float2*)&Bpf[nb2 + 8];
            split2(q0.x, q0.y, bh[ni][0], bl[ni][0]);
            split2(q1.x, q1.y, bh[ni][1], bl[ni][1]);
        }
        #pragma unroll
        for (int mi = 0; mi < 4; mi++)
            #pragma unroll
            for (int ni = 0; ni < 4; ni++) {
                mma_bf16(acc[mi][ni], ah[mi], bh[ni]);
                mma_bf16(acc[mi][ni], ah[mi], bl[ni]);
                mma_bf16(acc[mi][ni], al[mi], bh[ni]);
            }
    }

    __syncthreads();
    #pragma unroll
    for (int mi = 0; mi < 4; mi++) {
        int rr = bm + wm + 16 * mi + gr;
        #pragma unroll
        for (int ni = 0; ni < 4; ni++) {
            int col = bn + wn + 8 * ni + 2 * kq;
            float b0 = 0.f, b1 = 0.f;
            if (bias) { b0 = bias[col]; b1 = bias[col + 1]; }
            float v00 = acc[mi][ni][0] + b0, v01 = acc[mi][ni][1] + b1;
            float v10 = acc[mi][ni][2] + b0, v11 = acc[mi][ni][3] + b1;
            if (res) {
                v00 += res[(size_t)rr * N + col];
                v01 += res[(size_t)rr * N + col + 1];
                v10 += res[(size_t)(rr + 8) * N + col];
                v11 += res[(size_t)(rr + 8) * N + col + 1];
            }
            float2 lo; lo.x = v00; lo.y = v01;
            float2 hi; hi.x = v10; hi.y = v11;
            *(float2*)&C[(size_t)rr * N + col] = lo;
            *(float2*)&C[(size_t)(rr + 8) * N + col] = hi;
        }
    }
}

// ---------------- RoPE (in-place on q and k, [NTOK, D] layout) -------------------
__global__ __launch_bounds__(256) void rope_kernel(float* __restrict__ q, float* __restrict__ k)
{
    int gid = blockIdx.x * 256 + threadIdx.x;   // NTOK * 512 total
    int r   = gid >> 9;
    int rem = gid & 511;
    int h   = rem >> 5;
    int d   = rem & 31;
    int s   = r & (Sseq - 1);
    float inv = expf(-(float)d * (9.210340371976184f / 32.0f));
    float ang = (float)s * inv;
    float sn, cs;
    sincosf(ang, &sn, &cs);
    size_t base = (size_t)r * Dm + h * HDd + d;
    float q1 = q[base], q2 = q[base + 32];
    q[base]      = q1 * cs - q2 * sn;
    q[base + 32] = q2 * cs + q1 * sn;
    float k1 = k[base], k2 = k[base + 32];
    k[base]      = k1 * cs - k2 * sn;
    k[base + 32] = k2 * cs + k1 * sn;
}

// ---------------- Sliding-window attention ---------------------------------------
#define QT      64
#define KSPAN   320
#define PSTRIDE 321
#define TSTRIDE 68

__global__ __launch_bounds__(256) void attn_kernel(
    const float* __restrict__ q, const float* __restrict__ k, const float* __restrict__ v,
    float* __restrict__ attn, float* __restrict__ ctx)
{
    extern __shared__ float sm[];
    float* Ps = sm;                              // [64][321]
    float* Qs = sm + QT * PSTRIDE;               // [64 d][68]
    float* Cs = Qs + HDd * TSTRIDE;              // [64][68]

    int blk = blockIdx.x;
    int qt = blk & 15;
    int h  = (blk >> 4) & 15;
    int b  = blk >> 8;
    int q0 = qt * QT;
    int kb = q0 - (WIN - 1);
    int tid = threadIdx.x;
    int tx = tid & 15, ty = tid >> 4;
    const float scale = 0.125f;

    for (int idx = tid; idx < QT * HDd; idx += 256) {
        int qi = idx >> 6, d = idx & 63;
        Qs[d * TSTRIDE + qi] = q[(size_t)(b * Sseq + q0 + qi) * Dm + h * HDd + d];
    }

    for (int c = 0; c < 5; c++) {
        for (int idx = tid; idx < 64 * HDd; idx += 256) {
            int jj = idx >> 6, d = idx & 63;
            int jg = kb + c * 64 + jj;
            float kv = (jg >= 0 && jg < Sseq)
                       ? k[(size_t)(b * Sseq + jg) * Dm + h * HDd + d] : 0.f;
            Cs[d * TSTRIDE + jj] = kv;
        }
        __syncthreads();
        float acc[4][4] = {{0.f}};
        #pragma unroll 4
        for (int d = 0; d < HDd; d++) {
            float a4[4], b4[4];
            *(float4*)a4 = *(const float4*)&Qs[d * TSTRIDE + ty * 4];
            *(float4*)b4 = *(const float4*)&Cs[d * TSTRIDE + tx * 4];
            #pragma unroll
            for (int i = 0; i < 4; i++)
                #pragma unroll
                for (int jj = 0; jj < 4; jj++)
                    acc[i][jj] += a4[i] * b4[jj];
        }
        #pragma unroll
        for (int i = 0; i < 4; i++)
            #pragma unroll
            for (int jj = 0; jj < 4; jj++)
                Ps[(ty * 4 + i) * PSTRIDE + c * 64 + tx * 4 + jj] = acc[i][jj] * scale;
        __syncthreads();
    }

    int warp = tid >> 5, lane = tid & 31;
    for (int qi = warp; qi < QT; qi += 8) {
        int i = q0 + qi;
        int colLo = qi;
        if (-kb > colLo) colLo = -kb;
        int colHi = qi + (WIN - 1);
        float* prow = Ps + qi * PSTRIDE;
        float m = -1e30f;
        for (int c = lane; c < KSPAN; c += 32)
            if (c >= colLo && c <= colHi) m = fmaxf(m, prow[c]);
        #pragma unroll
        for (int off = 16; off > 0; off >>= 1)
            m = fmaxf(m, __shfl_xor_sync(0xffffffffu, m, off));
        float ssum = 0.f;
        for (int c = lane; c < KSPAN; c += 32) {
            float p = 0.f;
            if (c >= colLo && c <= colHi) p = __expf(prow[c] - m);
            prow[c] = p;
            ssum += p;
        }
        #pragma unroll
        for (int off = 16; off > 0; off >>= 1)
            ssum += __shfl_xor_sync(0xffffffffu, ssum, off);
        float inv = 1.f / ssum;
        float* arow = attn + ((size_t)((b * Hh + h) * Sseq + i)) * Sseq;
        for (int c = lane; c < KSPAN; c += 32) {
            float p = prow[c] * inv;
            prow[c] = p;
            if (c >= colLo && c <= colHi) arow[kb + c] = p;
        }
    }
    __syncthreads();

    float acc[4][4] = {{0.f}};
    for (int c = 0; c < 5; c++) {
        for (int idx = tid; idx < 64 * HDd; idx += 256) {
            int jj = idx >> 6, d = idx & 63;
            int jg = kb + c * 64 + jj;
            float vv = (jg >= 0 && jg < Sseq)
                       ? v[(size_t)(b * Sseq + jg) * Dm + h * HDd + d] : 0.f;
            Cs[jj * TSTRIDE + d] = vv;
        }
        __syncthreads();
        #pragma unroll 4
        for (int kk = 0; kk < 64; kk++) {
            float4 vv = *(const float4*)&Cs[kk * TSTRIDE + tx * 4];
            #pragma unroll
            for (int i = 0; i < 4; i++) {
                float p = Ps[(ty * 4 + i) * PSTRIDE + c * 64 + kk];
                acc[i][0] += p * vv.x;
                acc[i][1] += p * vv.y;
                acc[i][2] += p * vv.z;
                acc[i][3] += p * vv.w;
            }
        }
        __syncthreads();
    }
    #pragma unroll
    for (int i = 0; i < 4; i++) {
        int row = b * Sseq + q0 + ty * 4 + i;
        float4 o;
        o.x = roundtf(acc[i][0]); o.y = roundtf(acc[i][1]);
        o.z = roundtf(acc[i][2]); o.w = roundtf(acc[i][3]);
        *(float4*)&ctx[(size_t)row * Dm + h * HDd + tx * 4] = o;
    }
}

// ---------------- SiLU(gate) * up (tf32-rounded output) --------------------------
__global__ __launch_bounds__(256) void silu_mul_kernel(
    const float* __restrict__ g, const float* __restrict__ u, float* __restrict__ o, int n)
{
    int i = blockIdx.x * 256 + threadIdx.x;
    if (i < n) {
        float a = g[i];
        o[i] = roundtf(a / (1.f + expf(-a)) * u[i]);
    }
}

// ---------------- launch ---------------------------------------------------------
extern "C" void kernel_launch(void* const* d_in, const int* in_sizes, int n_in,
                              void* d_out, int out_size)
{
    const float* x   = (const float*)d_in[0];
    const float* wq  = (const float*)d_in[1];
    const float* bq  = (const float*)d_in[2];
    const float* wk  = (const float*)d_in[3];
    const float* bk  = (const float*)d_in[4];
    const float* wv  = (const float*)d_in[5];
    const float* bv  = (const float*)d_in[6];
    const float* wo  = (const float*)d_in[7];
    const float* bo  = (const float*)d_in[8];
    const float* anw = (const float*)d_in[9];
    const float* fnw = (const float*)d_in[10];
    const float* gw  = (const float*)d_in[11];
    const float* uw  = (const float*)d_in[12];
    const float* dw  = (const float*)d_in[13];

    float* out_x    = (float*)d_out;
    float* out_attn = out_x + (size_t)NTOK * Dm;

    float *h, *qp, *kp, *vp, *ctx, *x1, *h2, *gt, *up, *act;
    float *rwv, *rwo, *rgw, *ruw, *rdw;
    cudaGetSymbolAddress((void**)&h,   g_h);
    cudaGetSymbolAddress((void**)&qp,  g_q);
    cudaGetSymbolAddress((void**)&kp,  g_k);
    cudaGetSymbolAddress((void**)&vp,  g_v);
    cudaGetSymbolAddress((void**)&ctx, g_ctx);
    cudaGetSymbolAddress((void**)&x1,  g_x1);
    cudaGetSymbolAddress((void**)&h2,  g_h2);
    cudaGetSymbolAddress((void**)&gt,  g_gate);
    cudaGetSymbolAddress((void**)&up,  g_up);
    cudaGetSymbolAddress((void**)&act, g_act);
    cudaGetSymbolAddress((void**)&rwv, g_wv);
    cudaGetSymbolAddress((void**)&rwo, g_wo);
    cudaGetSymbolAddress((void**)&rgw, g_gw);
    cudaGetSymbolAddress((void**)&ruw, g_uw);
    cudaGetSymbolAddress((void**)&rdw, g_dw);

    // opt-in smem
    cudaFuncSetAttribute(gemm_tc_pipe,   cudaFuncAttributeMaxDynamicSharedMemorySize, SMEM_GEMM);
    cudaFuncSetAttribute(gemm_bf16_split, cudaFuncAttributeMaxDynamicSharedMemorySize, SMEM_GEMM);

    // pre-round x-path weights to tf32-rna (cheap; once per replay)
    round_tf32_kernel<<<(Dm * Dm / 4 + 255) / 256, 256>>>((const float4*)wv, (float4*)rwv, Dm * Dm / 4);
    round_tf32_kernel<<<(Dm * Dm / 4 + 255) / 256, 256>>>((const float4*)wo, (float4*)rwo, Dm * Dm / 4);
    round_tf32_kernel<<<(FFN_D * Dm / 4 + 255) / 256, 256>>>((const float4*)gw, (float4*)rgw, FFN_D * Dm / 4);
    round_tf32_kernel<<<(FFN_D * Dm / 4 + 255) / 256, 256>>>((const float4*)uw, (float4*)ruw, FFN_D * Dm / 4);
    round_tf32_kernel<<<(FFN_D * Dm / 4 + 255) / 256, 256>>>((const float4*)dw, (float4*)rdw, FFN_D * Dm / 4);

    // attn-norm (NOT rounded: feeds near-fp32 Q/K path)
    rmsnorm_kernel<<<NTOK, 256>>>(x, anw, h, 0);

    // QKV projections
    dim3 g1(Dm / TBN, NTOK / TBM);      // (8, 16)
    gemm_bf16_split<<<g1, 256, SMEM_GEMM>>>(h, wq, bq, nullptr, qp, NTOK, Dm, Dm);
    gemm_bf16_split<<<g1, 256, SMEM_GEMM>>>(h, wk, bk, nullptr, kp, NTOK, Dm, Dm);
    gemm_tc_pipe  <<<g1, 256, SMEM_GEMM>>>(h, rwv, bv, nullptr, vp, NTOK, Dm, Dm);

    // RoPE on q and k
    rope_kernel<<<(NTOK * 512) / 256, 256>>>(qp, kp);

    // zero dense attn output, then windowed attention
    cudaMemsetAsync(out_attn, 0, (size_t)Bsz * Hh * Sseq * Sseq * sizeof(float), 0);
    int smemBytes = (QT * PSTRIDE + 2 * 64 * TSTRIDE) * (int)sizeof(float);
    cudaFuncSetAttribute(attn_kernel, cudaFuncAttributeMaxDynamicSharedMemorySize, smemBytes);
    attn_kernel<<<Bsz * Hh * (Sseq / QT), 256, smemBytes>>>(qp, kp, vp, out_attn, ctx);

    // output projection + residual
    gemm_tc_pipe<<<g1, 256, SMEM_GEMM>>>(ctx, rwo, bo, x, x1, NTOK, Dm, Dm);

    // ffn-norm (rounded: feeds plain tf32 GEMMs)
    rmsnorm_kernel<<<NTOK, 256>>>(x1, fnw, h2, 1);

    // FFN
    dim3 g2(FFN_D / TBN, NTOK / TBM);   // (32, 16)
    gemm_tc_pipe<<<g2, 256, SMEM_GEMM>>>(h2, rgw, nullptr, nullptr, gt, NTOK, FFN_D, Dm);
    gemm_tc_pipe<<<g2, 256, SMEM_GEMM>>>(h2, ruw, nullptr, nullptr, up, NTOK, FFN_D, Dm);
    silu_mul_kernel<<<(NTOK * FFN_D) / 256, 256>>>(gt, up, act, NTOK * FFN_D);
    gemm_tc_pipe<<<g1, 256, SMEM_GEMM>>>(act, rdw, nullptr, x1, out_x, NTOK, Dm, FFN_D);
}

// round 14
// speedup vs baseline: 2.4918x; 1.0705x over previous
#include <cuda_runtime.h>
#include <math.h>
#include <stdint.h>

// Problem constants
#define Bsz   2
#define Sseq  1024
#define Dm    1024
#define Hh    16
#define HDd   64
#define WIN   256
#define FFN_D 4096
#define NTOK  (Bsz * Sseq)   // 2048

// ---------------- scratch (no allocation allowed -> __device__ globals) ----------
__device__ float g_h   [NTOK * Dm];
__device__ float g_q   [NTOK * Dm];
__device__ float g_k   [NTOK * Dm];
__device__ float g_v   [NTOK * Dm];
__device__ float g_ctx [NTOK * Dm];
__device__ float g_x1  [NTOK * Dm];
__device__ float g_h2  [NTOK * Dm];
__device__ float g_gate[NTOK * FFN_D];
__device__ float g_act [NTOK * FFN_D];

// ---------------- helpers --------------------------------------------------------
__device__ __forceinline__ uint32_t f2tf32(float f) {
    uint32_t r;
    asm("cvt.rna.tf32.f32 %0, %1;" : "=r"(r) : "f"(f));
    return r;
}
__device__ __forceinline__ float roundtf(float f) { return __uint_as_float(f2tf32(f)); }

__device__ __forceinline__ void mma_tf32(float* c, const uint32_t* a, const uint32_t* b) {
    asm volatile(
        "mma.sync.aligned.m16n8k8.row.col.f32.tf32.tf32.f32 "
        "{%0,%1,%2,%3}, {%4,%5,%6,%7}, {%8,%9}, {%0,%1,%2,%3};\n"
        : "+f"(c[0]), "+f"(c[1]), "+f"(c[2]), "+f"(c[3])
        : "r"(a[0]), "r"(a[1]), "r"(a[2]), "r"(a[3]), "r"(b[0]), "r"(b[1]));
}
__device__ __forceinline__ void mma_bf16(float* c, const uint32_t* a, const uint32_t* b) {
    asm volatile(
        "mma.sync.aligned.m16n8k16.row.col.f32.bf16.bf16.f32 "
        "{%0,%1,%2,%3}, {%4,%5,%6,%7}, {%8,%9}, {%0,%1,%2,%3};\n"
        : "+f"(c[0]), "+f"(c[1]), "+f"(c[2]), "+f"(c[3])
        : "r"(a[0]), "r"(a[1]), "r"(a[2]), "r"(a[3]), "r"(b[0]), "r"(b[1]));
}

__device__ __forceinline__ uint32_t packbf(float lo, float hi) {
    uint32_t r;
    asm("cvt.rn.bf16x2.f32 %0, %1, %2;" : "=r"(r) : "f"(hi), "f"(lo));
    return r;
}
// split (x,y) into packed bf16x2 hi + lo (a = hi + lo to ~2^-18)
__device__ __forceinline__ void split2(float x, float y, uint32_t& hi, uint32_t& lo) {
    hi = packbf(x, y);
    float hx = __uint_as_float(hi << 16);
    float hy = __uint_as_float(hi & 0xFFFF0000u);
    lo = packbf(x - hx, y - hy);
}

__device__ __forceinline__ void cp16(uint32_t saddr, const void* g) {
    asm volatile("cp.async.cg.shared.global [%0], [%1], 16;\n" :: "r"(saddr), "l"(g));
}
__device__ __forceinline__ void cp_commit() {
    asm volatile("cp.async.commit_group;\n");
}
template<int N>
__device__ __forceinline__ void cp_wait() {
    asm volatile("cp.async.wait_group %0;\n" :: "n"(N));
}

// ---------------- RMSNorm: one block per token row ------------------------------
__global__ __launch_bounds__(256) void rmsnorm_kernel(
    const float* __restrict__ x, const float* __restrict__ w, float* __restrict__ o,
    int doRound)
{
    int row = blockIdx.x;
    const float* xr = x + (size_t)row * Dm;
    float vals[4];
    float s = 0.f;
    int j = 0;
    for (int i = threadIdx.x; i < Dm; i += 256, j++) {
        float vv = xr[i];
        vals[j] = vv;
        s += vv * vv;
    }
    #pragma unroll
    for (int off = 16; off > 0; off >>= 1)
        s += __shfl_xor_sync(0xffffffffu, s, off);
    __shared__ float red[8];
    if ((threadIdx.x & 31) == 0) red[threadIdx.x >> 5] = s;
    __syncthreads();
    float tot = 0.f;
    #pragma unroll
    for (int i = 0; i < 8; i++) tot += red[i];
    float sc = rsqrtf(tot * (1.0f / Dm) + 1e-6f);
    float* orow = o + (size_t)row * Dm;
    j = 0;
    for (int i = threadIdx.x; i < Dm; i += 256, j++) {
        float r = vals[j] * sc * w[i];
        orow[i] = doRound ? roundtf(r) : r;
    }
}

#define TBM 128
#define TBN 128
#define TBK 16
#define TS  20         // smem row stride in words
#define NSTG 4         // pipeline stages
#define STGW (TBM * TS)          // words per operand per stage
#define SMEM_GEMM (NSTG * 2 * STGW * 4)  // bytes

// ================= 4-stage pipelined tf32 GEMM ===================================
// C[M,N] = A[M,K]*B[N,K]^T. Activations pre-rounded rna, weights truncated by HMMA.
// MODE 0: +bias, +res (residual add).   MODE 1: C = rna( silu(res) * acc )  (FFN).
template<int MODE>
__global__ __launch_bounds__(256, 2) void gemm_tc_pipe(
    const float* __restrict__ A, const float* __restrict__ B,
    const float* __restrict__ bias, const float* __restrict__ res,
    float* __restrict__ C, int M, int N, int K)
{
    extern __shared__ uint32_t smem_u[];
    uint32_t* As = smem_u;                 // [NSTG][STGW]
    uint32_t* Bs = smem_u + NSTG * STGW;   // [NSTG][STGW]

    int tid  = threadIdx.x;
    int lane = tid & 31, warp = tid >> 5;
    int wm = (warp & 1) * 64;
    int wn = (warp >> 1) * 32;
    int bm = blockIdx.y * TBM, bn = blockIdx.x * TBN;
    int gr = lane >> 2, kq = lane & 3;

    float acc[4][4][4];
    #pragma unroll
    for (int mi = 0; mi < 4; mi++)
        #pragma unroll
        for (int ni = 0; ni < 4; ni++)
            #pragma unroll
            for (int t = 0; t < 4; t++) acc[mi][ni][t] = 0.f;

    const float* Ab = A + (size_t)bm * K;
    const float* Bb = B + (size_t)bn * K;

    int r0 = tid >> 2;                 // 0..63
    int c4 = (tid & 3) << 2;           // 0,4,8,12
    uint32_t sAb = (uint32_t)__cvta_generic_to_shared(As);
    uint32_t sBb = (uint32_t)__cvta_generic_to_shared(Bs);
    uint32_t off0 = (uint32_t)(r0 * TS + c4) * 4u;
    uint32_t off1 = (uint32_t)((r0 + 64) * TS + c4) * 4u;

    int nt = K / TBK;

    // prologue: tiles 0..NSTG-2
    #pragma unroll
    for (int p = 0; p < NSTG - 1; p++) {
        int k0 = p * TBK;
        uint32_t sa = sAb + p * STGW * 4, sb = sBb + p * STGW * 4;
        cp16(sa + off0, Ab + (size_t)r0 * K + k0 + c4);
        cp16(sa + off1, Ab + (size_t)(r0 + 64) * K + k0 + c4);
        cp16(sb + off0, Bb + (size_t)r0 * K + k0 + c4);
        cp16(sb + off1, Bb + (size_t)(r0 + 64) * K + k0 + c4);
        cp_commit();
    }

    for (int t = 0; t < nt; t++) {
        int buf = t & (NSTG - 1);
        cp_wait<NSTG - 2>();
        __syncthreads();

        // issue tile t+NSTG-1 into buffer freed at iteration t-1
        int tn = t + NSTG - 1;
        if (tn < nt) {
            int nb = tn & (NSTG - 1);
            int k0 = tn * TBK;
            uint32_t sa = sAb + nb * STGW * 4, sb = sBb + nb * STGW * 4;
            cp16(sa + off0, Ab + (size_t)r0 * K + k0 + c4);
            cp16(sa + off1, Ab + (size_t)(r0 + 64) * K + k0 + c4);
            cp16(sb + off0, Bb + (size_t)r0 * K + k0 + c4);
            cp16(sb + off1, Bb + (size_t)(r0 + 64) * K + k0 + c4);
        }
        cp_commit();

        const uint32_t* Ap = As + buf * STGW;
        const uint32_t* Bp = Bs + buf * STGW;
        #pragma unroll
        for (int ks = 0; ks < TBK; ks += 8) {
            uint32_t af[4][4], bf[4][2];
            #pragma unroll
            for (int mi = 0; mi < 4; mi++) {
                int ra = (wm + 16 * mi + gr) * TS + ks + kq;
                af[mi][0] = Ap[ra];
                af[mi][1] = Ap[ra + 8 * TS];
                af[mi][2] = Ap[ra + 4];
                af[mi][3] = Ap[ra + 8 * TS + 4];
            }
            #pragma unroll
            for (int ni = 0; ni < 4; ni++) {
                int rb = (wn + 8 * ni + gr) * TS + ks + kq;
                bf[ni][0] = Bp[rb];
                bf[ni][1] = Bp[rb + 4];
            }
            #pragma unroll
            for (int mi = 0; mi < 4; mi++)
                #pragma unroll
                for (int ni = 0; ni < 4; ni++)
                    mma_tf32(acc[mi][ni], af[mi], bf[ni]);
        }
    }

    __syncthreads();
    // ---- epilogue ----
    #pragma unroll
    for (int mi = 0; mi < 4; mi++) {
        int rr = bm + wm + 16 * mi + gr;
        #pragma unroll
        for (int ni = 0; ni < 4; ni++) {
            int col = bn + wn + 8 * ni + 2 * kq;
            float v00 = acc[mi][ni][0], v01 = acc[mi][ni][1];
            float v10 = acc[mi][ni][2], v11 = acc[mi][ni][3];
            if (MODE == 0) {
                if (bias) { v00 += bias[col]; v01 += bias[col + 1];
                            v10 += bias[col]; v11 += bias[col + 1]; }
                if (res) {
                    v00 += res[(size_t)rr * N + col];
                    v01 += res[(size_t)rr * N + col + 1];
                    v10 += res[(size_t)(rr + 8) * N + col];
                    v11 += res[(size_t)(rr + 8) * N + col + 1];
                }
            } else {
                // silu(gate) * up, rna-rounded
                float g00 = res[(size_t)rr * N + col];
                float g01 = res[(size_t)rr * N + col + 1];
                float g10 = res[(size_t)(rr + 8) * N + col];
                float g11 = res[(size_t)(rr + 8) * N + col + 1];
                v00 = roundtf(g00 / (1.f + expf(-g00)) * v00);
                v01 = roundtf(g01 / (1.f + expf(-g01)) * v01);
                v10 = roundtf(g10 / (1.f + expf(-g10)) * v10);
                v11 = roundtf(g11 / (1.f + expf(-g11)) * v11);
            }
            float2 lo; lo.x = v00; lo.y = v01;
            float2 hi; hi.x = v10; hi.y = v11;
            *(float2*)&C[(size_t)rr * N + col] = lo;
            *(float2*)&C[(size_t)(rr + 8) * N + col] = hi;
        }
    }
}

// ================= 4-stage pipelined bf16 3-term split GEMM (Q,K) ================
// Near-fp32 accuracy: a*b ~= ah*bh + ah*bl + al*bh  (error ~2^-18 rel).
__global__ __launch_bounds__(256) void gemm_bf16_split(
    const float* __restrict__ A, const float* __restrict__ B,
    const float* __restrict__ bias, const float* __restrict__ res,
    float* __restrict__ C, int M, int N, int K)
{
    extern __shared__ uint32_t smem_u[];
    uint32_t* As = smem_u;
    uint32_t* Bs = smem_u + NSTG * STGW;

    int tid  = threadIdx.x;
    int lane = tid & 31, warp = tid >> 5;
    int wm = (warp & 1) * 64;
    int wn = (warp >> 1) * 32;
    int bm = blockIdx.y * TBM, bn = blockIdx.x * TBN;
    int gr = lane >> 2, kq = lane & 3;

    float acc[4][4][4];
    #pragma unroll
    for (int mi = 0; mi < 4; mi++)
        #pragma unroll
        for (int ni = 0; ni < 4; ni++)
            #pragma unroll
            for (int t = 0; t < 4; t++) acc[mi][ni][t] = 0.f;

    const float* Ab = A + (size_t)bm * K;
    const float* Bb = B + (size_t)bn * K;

    int r0 = tid >> 2;
    int c4 = (tid & 3) << 2;
    uint32_t sAb = (uint32_t)__cvta_generic_to_shared(As);
    uint32_t sBb = (uint32_t)__cvta_generic_to_shared(Bs);
    uint32_t off0 = (uint32_t)(r0 * TS + c4) * 4u;
    uint32_t off1 = (uint32_t)((r0 + 64) * TS + c4) * 4u;

    int nt = K / TBK;

    #pragma unroll
    for (int p = 0; p < NSTG - 1; p++) {
        int k0 = p * TBK;
        uint32_t sa = sAb + p * STGW * 4, sb = sBb + p * STGW * 4;
        cp16(sa + off0, Ab + (size_t)r0 * K + k0 + c4);
        cp16(sa + off1, Ab + (size_t)(r0 + 64) * K + k0 + c4);
        cp16(sb + off0, Bb + (size_t)r0 * K + k0 + c4);
        cp16(sb + off1, Bb + (size_t)(r0 + 64) * K + k0 + c4);
        cp_commit();
    }

    for (int t = 0; t < nt; t++) {
        int buf = t & (NSTG - 1);
        cp_wait<NSTG - 2>();
        __syncthreads();

        int tn = t + NSTG - 1;
        if (tn < nt) {
            int nb = tn & (NSTG - 1);
            int k0 = tn * TBK;
            uint32_t sa = sAb + nb * STGW * 4, sb = sBb + nb * STGW * 4;
            cp16(sa + off0, Ab + (size_t)r0 * K + k0 + c4);
            cp16(sa + off1, Ab + (size_t)(r0 + 64) * K + k0 + c4);
            cp16(sb + off0, Bb + (size_t)r0 * K + k0 + c4);
            cp16(sb + off1, Bb + (size_t)(r0 + 64) * K + k0 + c4);
        }
        cp_commit();

        const float* Apf = (const float*)(As + buf * STGW);
        const float* Bpf = (const float*)(Bs + buf * STGW);

        // one k16 step per tile
        uint32_t ah[4][4], al[4][4], bh[4][2], bl[4][2];
        #pragma unroll
        for (int mi = 0; mi < 4; mi++) {
            int rbase = (wm + 16 * mi + gr) * TS + 2 * kq;
            float2 p0 = *(const float2*)&Apf[rbase];
            float2 p1 = *(const float2*)&Apf[rbase + 8 * TS];
            float2 p2 = *(const float2*)&Apf[rbase + 8];
            float2 p3 = *(const float2*)&Apf[rbase + 8 * TS + 8];
            split2(p0.x, p0.y, ah[mi][0], al[mi][0]);
            split2(p1.x, p1.y, ah[mi][1], al[mi][1]);
            split2(p2.x, p2.y, ah[mi][2], al[mi][2]);
            split2(p3.x, p3.y, ah[mi][3], al[mi][3]);
        }
        #pragma unroll
        for (int ni = 0; ni < 4; ni++) {
            int nb2 = (wn + 8 * ni + gr) * TS + 2 * kq;
            float2 q0 = *(const float2*)&Bpf[nb2];
            float2 q1 = *(const float2*)&Bpf[nb2 + 8];
            split2(q0.x, q0.y, bh[ni][0], bl[ni][0]);
            split2(q1.x, q1.y, bh[ni][1], bl[ni][1]);
        }
        #pragma unroll
        for (int mi = 0; mi < 4; mi++)
            #pragma unroll
            for (int ni = 0; ni < 4; ni++) {
                mma_bf16(acc[mi][ni], ah[mi], bh[ni]);
                mma_bf16(acc[mi][ni], ah[mi], bl[ni]);
                mma_bf16(acc[mi][ni], al[mi], bh[ni]);
            }
    }

    __syncthreads();
    #pragma unroll
    for (int mi = 0; mi < 4; mi++) {
        int rr = bm + wm + 16 * mi + gr;
        #pragma unroll
        for (int ni = 0; ni < 4; ni++) {
            int col = bn + wn + 8 * ni + 2 * kq;
            float b0 = 0.f, b1 = 0.f;
            if (bias) { b0 = bias[col]; b1 = bias[col + 1]; }
            float v00 = acc[mi][ni][0] + b0, v01 = acc[mi][ni][1] + b1;
            float v10 = acc[mi][ni][2] + b0, v11 = acc[mi][ni][3] + b1;
            if (res) {
                v00 += res[(size_t)rr * N + col];
                v01 += res[(size_t)rr * N + col + 1];
                v10 += res[(size_t)(rr + 8) * N + col];
                v11 += res[(size_t)(rr + 8) * N + col + 1];
            }
            float2 lo; lo.x = v00; lo.y = v01;
            float2 hi; hi.x = v10; hi.y = v11;
            *(float2*)&C[(size_t)rr * N + col] = lo;
            *(float2*)&C[(size_t)(rr + 8) * N + col] = hi;
        }
    }
}

// ---------------- RoPE (in-place on q and k, [NTOK, D] layout) -------------------
__global__ __launch_bounds__(256) void rope_kernel(float* __restrict__ q, float* __restrict__ k)
{
    int gid = blockIdx.x * 256 + threadIdx.x;   // NTOK * 512 total
    int r   = gid >> 9;
    int rem = gid & 511;
    int h   = rem >> 5;
    int d   = rem & 31;
    int s   = r & (Sseq - 1);
    float inv = expf(-(float)d * (9.210340371976184f / 32.0f));
    float ang = (float)s * inv;
    float sn, cs;
    sincosf(ang, &sn, &cs);
    size_t base = (size_t)r * Dm + h * HDd + d;
    float q1 = q[base], q2 = q[base + 32];
    q[base]      = q1 * cs - q2 * sn;
    q[base + 32] = q2 * cs + q1 * sn;
    float k1 = k[base], k2 = k[base + 32];
    k[base]      = k1 * cs - k2 * sn;
    k[base + 32] = k2 * cs + k1 * sn;
}

// ---------------- Sliding-window attention (writes FULL dense prob rows) ---------
#define QT      64
#define KSPAN   320
#define PSTRIDE 321
#define TSTRIDE 68

__global__ __launch_bounds__(256) void attn_kernel(
    const float* __restrict__ q, const float* __restrict__ k, const float* __restrict__ v,
    float* __restrict__ attn, float* __restrict__ ctx)
{
    extern __shared__ float sm[];
    float* Ps = sm;                              // [64][321]
    float* Qs = sm + QT * PSTRIDE;               // [64 d][68]
    float* Cs = Qs + HDd * TSTRIDE;              // [64][68]

    int blk = blockIdx.x;
    int qt = blk & 15;
    int h  = (blk >> 4) & 15;
    int b  = blk >> 8;
    int q0 = qt * QT;
    int kb = q0 - (WIN - 1);
    int tid = threadIdx.x;
    int tx = tid & 15, ty = tid >> 4;
    const float scale = 0.125f;

    for (int idx = tid; idx < QT * HDd; idx += 256) {
        int qi = idx >> 6, d = idx & 63;
        Qs[d * TSTRIDE + qi] = q[(size_t)(b * Sseq + q0 + qi) * Dm + h * HDd + d];
    }

    for (int c = 0; c < 5; c++) {
        for (int idx = tid; idx < 64 * HDd; idx += 256) {
            int jj = idx >> 6, d = idx & 63;
            int jg = kb + c * 64 + jj;
            float kv = (jg >= 0 && jg < Sseq)
                       ? k[(size_t)(b * Sseq + jg) * Dm + h * HDd + d] : 0.f;
            Cs[d * TSTRIDE + jj] = kv;
        }
        __syncthreads();
        float acc[4][4] = {{0.f}};
        #pragma unroll 4
        for (int d = 0; d < HDd; d++) {
            float a4[4], b4[4];
            *(float4*)a4 = *(const float4*)&Qs[d * TSTRIDE + ty * 4];
            *(float4*)b4 = *(const float4*)&Cs[d * TSTRIDE + tx * 4];
            #pragma unroll
            for (int i = 0; i < 4; i++)
                #pragma unroll
                for (int jj = 0; jj < 4; jj++)
                    acc[i][jj] += a4[i] * b4[jj];
        }
        #pragma unroll
        for (int i = 0; i < 4; i++)
            #pragma unroll
            for (int jj = 0; jj < 4; jj++)
                Ps[(ty * 4 + i) * PSTRIDE + c * 64 + tx * 4 + jj] = acc[i][jj] * scale;
        __syncthreads();
    }

    int warp = tid >> 5, lane = tid & 31;
    for (int qi = warp; qi < QT; qi += 8) {
        int i = q0 + qi;
        int colLo = qi;
        if (-kb > colLo) colLo = -kb;            // window start (smem col)
        int colHi = qi + (WIN - 1);              // window end (smem col)
        float* prow = Ps + qi * PSTRIDE;
        float m = -1e30f;
        for (int c = lane; c < KSPAN; c += 32)
            if (c >= colLo && c <= colHi) m = fmaxf(m, prow[c]);
        #pragma unroll
        for (int off = 16; off > 0; off >>= 1)
            m = fmaxf(m, __shfl_xor_sync(0xffffffffu, m, off));
        float ssum = 0.f;
        for (int c = lane; c < KSPAN; c += 32) {
            float p = 0.f;
            if (c >= colLo && c <= colHi) p = __expf(prow[c] - m);
            prow[c] = p;
            ssum += p;
        }
        #pragma unroll
        for (int off = 16; off > 0; off >>= 1)
            ssum += __shfl_xor_sync(0xffffffffu, ssum, off);
        float inv = 1.f / ssum;
        // normalize probs in smem for phase 3
        for (int c = lane; c < KSPAN; c += 32)
            prow[c] *= inv;
        __syncwarp();
        // write FULL dense row: zeros outside window (replaces global memset)
        int jLo = kb + colLo;                    // global col of window start
        float* arow = attn + ((size_t)((b * Hh + h) * Sseq + i)) * Sseq;
        for (int j4 = lane * 4; j4 < Sseq; j4 += 128) {
            float4 o;
            #pragma unroll
            for (int t = 0; t < 4; t++) {
                int j = j4 + t;
                float p = 0.f;
                if (j >= jLo && j <= i) p = prow[j - kb];
                ((float*)&o)[t] = p;
            }
            *(float4*)&arow[j4] = o;
        }
    }
    __syncthreads();

    float acc[4][4] = {{0.f}};
    for (int c = 0; c < 5; c++) {
        for (int idx = tid; idx < 64 * HDd; idx += 256) {
            int jj = idx >> 6, d = idx & 63;
            int jg = kb + c * 64 + jj;
            float vv = (jg >= 0 && jg < Sseq)
                       ? v[(size_t)(b * Sseq + jg) * Dm + h * HDd + d] : 0.f;
            Cs[jj * TSTRIDE + d] = vv;
        }
        __syncthreads();
        #pragma unroll 4
        for (int kk = 0; kk < 64; kk++) {
            float4 vv = *(const float4*)&Cs[kk * TSTRIDE + tx * 4];
            #pragma unroll
            for (int i = 0; i < 4; i++) {
                float p = Ps[(ty * 4 + i) * PSTRIDE + c * 64 + kk];
                acc[i][0] += p * vv.x;
                acc[i][1] += p * vv.y;
                acc[i][2] += p * vv.z;
                acc[i][3] += p * vv.w;
            }
        }
        __syncthreads();
    }
    #pragma unroll
    for (int i = 0; i < 4; i++) {
        int row = b * Sseq + q0 + ty * 4 + i;
        float4 o;
        o.x = roundtf(acc[i][0]); o.y = roundtf(acc[i][1]);
        o.z = roundtf(acc[i][2]); o.w = roundtf(acc[i][3]);
        *(float4*)&ctx[(size_t)row * Dm + h * HDd + tx * 4] = o;
    }
}

// ---------------- launch ---------------------------------------------------------
extern "C" void kernel_launch(void* const* d_in, const int* in_sizes, int n_in,
                              void* d_out, int out_size)
{
    const float* x   = (const float*)d_in[0];
    const float* wq  = (const float*)d_in[1];
    const float* bq  = (const float*)d_in[2];
    const float* wk  = (const float*)d_in[3];
    const float* bk  = (const float*)d_in[4];
    const float* wv  = (const float*)d_in[5];
    const float* bv  = (const float*)d_in[6];
    const float* wo  = (const float*)d_in[7];
    const float* bo  = (const float*)d_in[8];
    const float* anw = (const float*)d_in[9];
    const float* fnw = (const float*)d_in[10];
    const float* gw  = (const float*)d_in[11];
    const float* uw  = (const float*)d_in[12];
    const float* dw  = (const float*)d_in[13];

    float* out_x    = (float*)d_out;
    float* out_attn = out_x + (size_t)NTOK * Dm;

    float *h, *qp, *kp, *vp, *ctx, *x1, *h2, *gt, *act;
    cudaGetSymbolAddress((void**)&h,   g_h);
    cudaGetSymbolAddress((void**)&qp,  g_q);
    cudaGetSymbolAddress((void**)&kp,  g_k);
    cudaGetSymbolAddress((void**)&vp,  g_v);
    cudaGetSymbolAddress((void**)&ctx, g_ctx);
    cudaGetSymbolAddress((void**)&x1,  g_x1);
    cudaGetSymbolAddress((void**)&h2,  g_h2);
    cudaGetSymbolAddress((void**)&gt,  g_gate);
    cudaGetSymbolAddress((void**)&act, g_act);

    // opt-in smem
    cudaFuncSetAttribute(gemm_tc_pipe<0>, cudaFuncAttributeMaxDynamicSharedMemorySize, SMEM_GEMM);
    cudaFuncSetAttribute(gemm_tc_pipe<1>, cudaFuncAttributeMaxDynamicSharedMemorySize, SMEM_GEMM);
    cudaFuncSetAttribute(gemm_bf16_split, cudaFuncAttributeMaxDynamicSharedMemorySize, SMEM_GEMM);

    // attn-norm (NOT rounded: feeds near-fp32 Q/K path)
    rmsnorm_kernel<<<NTOK, 256>>>(x, anw, h, 0);

    // QKV projections
    dim3 g1(Dm / TBN, NTOK / TBM);      // (8, 16)
    gemm_bf16_split<<<g1, 256, SMEM_GEMM>>>(h, wq, bq, nullptr, qp, NTOK, Dm, Dm);
    gemm_bf16_split<<<g1, 256, SMEM_GEMM>>>(h, wk, bk, nullptr, kp, NTOK, Dm, Dm);
    gemm_tc_pipe<0><<<g1, 256, SMEM_GEMM>>>(h, wv, bv, nullptr, vp, NTOK, Dm, Dm);

    // RoPE on q and k
    rope_kernel<<<(NTOK * 512) / 256, 256>>>(qp, kp);

    // windowed attention (writes full dense prob rows; no memset needed)
    int smemBytes = (QT * PSTRIDE + 2 * 64 * TSTRIDE) * (int)sizeof(float);
    cudaFuncSetAttribute(attn_kernel, cudaFuncAttributeMaxDynamicSharedMemorySize, smemBytes);
    attn_kernel<<<Bsz * Hh * (Sseq / QT), 256, smemBytes>>>(qp, kp, vp, out_attn, ctx);

    // output projection + residual
    gemm_tc_pipe<0><<<g1, 256, SMEM_GEMM>>>(ctx, wo, bo, x, x1, NTOK, Dm, Dm);

    // ffn-norm (rounded: feeds plain tf32 GEMMs)
    rmsnorm_kernel<<<NTOK, 256>>>(x1, fnw, h2, 1);

    // FFN: gate GEMM (raw fp32 out), then up GEMM with fused silu(gate)*up epilogue
    dim3 g2(FFN_D / TBN, NTOK / TBM);   // (32, 16)
    gemm_tc_pipe<0><<<g2, 256, SMEM_GEMM>>>(h2, gw, nullptr, nullptr, gt, NTOK, FFN_D, Dm);
    gemm_tc_pipe<1><<<g2, 256, SMEM_GEMM>>>(h2, uw, nullptr, gt, act, NTOK, FFN_D, Dm);
    // down projection + residual -> out_x
    gemm_tc_pipe<0><<<g1, 256, SMEM_GEMM>>>(act, dw, nullptr, x1, out_x, NTOK, Dm, FFN_D);
}